// round 13
// baseline (speedup 1.0000x reference)
#include <cuda_runtime.h>
#include <cuda_fp16.h>
#include <cstdint>
#include <math.h>

// ---------------- problem constants ----------------
#define BB   1024
#define IMG  512
#define TXT  300
#define NN   14
#define FF   2048
#define HID  128
#define CC   14
#define EE   182
#define DD   812     // IMG + TXT
#define D3   2436    // 3*D
#define MM   (BB*NN) // 14336 rows
#define DP   816     // DD padded to mult of 8
#define QLD  2448    // 3*DP, qkv fp16 row stride

// ---------------- fp32 scratch ----------------
__device__ float g_qkvi[(size_t)BB * D3];
__device__ float g_qkvt[(size_t)NN * D3];
__device__ float g_S0  [(size_t)BB * BB];
__device__ float g_Bq  [(size_t)NN * BB];
__device__ float g_ovt [(size_t)NN * DD];
__device__ float g_ao2 [(size_t)MM * DD];
__device__ float g_x1  [(size_t)MM * DD];
__device__ float g_ff  [(size_t)MM * DD];
__device__ float g_g1  [(size_t)MM * HID];
__device__ float g_gsum[(size_t)BB * HID];
__device__ float g_pool[(size_t)BB * HID];

// ---------------- fp16 scratch (tensor-core operands) ----------------
__device__ __align__(256) __half g_imgr_h [(size_t)BB * IMG];
__device__ __align__(256) __half g_inwr_h [(size_t)D3 * IMG];
__device__ __align__(256) __half g_outwr_h[(size_t)DD * DP];
__device__ __align__(256) __half g_qkvi_h [(size_t)BB * QLD];
__device__ __align__(256) __half g_VoT_h  [(size_t)DD * BB];
__device__ __align__(256) __half g_attn_h [(size_t)NN * BB * BB];
__device__ __align__(256) __half g_x1r_h  [(size_t)MM * DP];
__device__ __align__(256) __half g_w1t_h  [(size_t)FF * DP];
__device__ __align__(256) __half g_hid_h  [(size_t)MM * FF];
__device__ __align__(256) __half g_w2t_h  [(size_t)DD * FF];
__device__ __align__(256) __half g_x2_h   [(size_t)MM * DP];
__device__ __align__(256) __half g_gw1t_h [(size_t)HID * DP];

__device__ int   g_eoff[NN + 1];
__device__ int   g_esrc[EE + NN + 16];
__device__ float g_ewt [EE + NN + 16];
__device__ float g_cmean[NN];

// ================= fp16 mma.sync GEMM (cp.async, 3-stage, BT only) ==========
#define CA_STAGES 3
template <int IM> struct CAC {
    static const int A_U32 = IM * 64 * 20;
    static const int STAGE_U32 = A_U32 + 2560;
    static const int SMEM = CA_STAGES * STAGE_U32 * 4;
};

template <int IM>
__device__ __forceinline__ void hfetch(
    int k0, int M, int N, int K,
    const __half* __restrict__ A, long long lda,
    const __half* __restrict__ B, long long ldb,
    int m0, int n0, int tid, uint32_t sA, uint32_t sB) {
    if (IM == 2) {
        int row = tid >> 1, c = tid & 1;
        int gm = m0 + row;
        bool mv = gm < M;
        const __half* rp = A + (long long)(mv ? gm : m0) * lda;
#pragma unroll
        for (int h = 0; h < 2; h++) {
            int kh = k0 + c * 16 + h * 8;
            int rem = K - kh;
            int vb = mv ? (rem >= 8 ? 16 : (rem > 0 ? rem * 2 : 0)) : 0;
            const __half* src = rp + (kh < K ? kh : 0);
            uint32_t dst = sA + (uint32_t)(row * 20 + c * 8 + h * 4) * 4u;
            asm volatile("cp.async.cg.shared.global [%0], [%1], 16, %2;"
                         :: "r"(dst), "l"(src), "r"(vb));
        }
    } else {
        int row = tid >> 2, c = tid & 3;
        int gm = m0 + row;
        bool mv = gm < M;
        const __half* rp = A + (long long)(mv ? gm : m0) * lda;
        int kh = k0 + c * 8;
        int rem = K - kh;
        int vb = mv ? (rem >= 8 ? 16 : (rem > 0 ? rem * 2 : 0)) : 0;
        const __half* src = rp + (kh < K ? kh : 0);
        uint32_t dst = sA + (uint32_t)(row * 20 + c * 4) * 4u;
        asm volatile("cp.async.cg.shared.global [%0], [%1], 16, %2;"
                     :: "r"(dst), "l"(src), "r"(vb));
    }
    {
        int row = tid >> 1, c = tid & 1;
        int gj = n0 + row;
        bool nv = gj < N;
        const __half* rp = B + (long long)(nv ? gj : n0) * ldb;
#pragma unroll
        for (int h = 0; h < 2; h++) {
            int kh = k0 + c * 16 + h * 8;
            int rem = K - kh;
            int vb = nv ? (rem >= 8 ? 16 : (rem > 0 ? rem * 2 : 0)) : 0;
            const __half* src = rp + (kh < K ? kh : 0);
            uint32_t dst = sB + (uint32_t)(row * 20 + c * 8 + h * 4) * 4u;
            asm volatile("cp.async.cg.shared.global [%0], [%1], 16, %2;"
                         :: "r"(dst), "l"(src), "r"(vb));
        }
    }
}

template <int IM>
__device__ __forceinline__ void hg_core(
    int M, int N, int K,
    const __half* __restrict__ A, long long lda,
    const __half* __restrict__ B, long long ldb,
    float* __restrict__ C, long long ldc,
    __half* __restrict__ Ch, long long ldh,
    const float* __restrict__ bias,
    int relu, int qkvpad,
    int m0, int n0, uint32_t* dsm) {
    if (m0 >= M) return;
    int tid = threadIdx.x;
    int warp = tid >> 5, lane = tid & 31;
    int wm = warp >> 1, wn = warp & 1;
    int gid = lane >> 2, tig = lane & 3;

    uint32_t smem_base = (uint32_t)__cvta_generic_to_shared(dsm);

    float c[IM][8][4];
#pragma unroll
    for (int i = 0; i < IM; i++)
#pragma unroll
        for (int j = 0; j < 8; j++)
#pragma unroll
            for (int r = 0; r < 4; r++) c[i][j][r] = 0.f;

    int ntiles = (K + 31) >> 5;

#pragma unroll
    for (int t = 0; t < CA_STAGES - 1; t++) {
        if (t < ntiles) {
            uint32_t sa = smem_base + (uint32_t)(t * CAC<IM>::STAGE_U32) * 4u;
            hfetch<IM>(t * 32, M, N, K, A, lda, B, ldb, m0, n0, tid,
                       sa, sa + (uint32_t)CAC<IM>::A_U32 * 4u);
        }
        asm volatile("cp.async.commit_group;");
    }

    for (int t = 0; t < ntiles; t++) {
        asm volatile("cp.async.wait_group %0;" :: "n"(CA_STAGES - 2));
        __syncthreads();

        int nf = t + CA_STAGES - 1;
        if (nf < ntiles) {
            uint32_t sa = smem_base +
                (uint32_t)((nf % CA_STAGES) * CAC<IM>::STAGE_U32) * 4u;
            hfetch<IM>(nf * 32, M, N, K, A, lda, B, ldb, m0, n0, tid,
                       sa, sa + (uint32_t)CAC<IM>::A_U32 * 4u);
        }
        asm volatile("cp.async.commit_group;");

        const uint32_t* sAu = dsm + (t % CA_STAGES) * CAC<IM>::STAGE_U32;
        const uint32_t* sBu = sAu + CAC<IM>::A_U32;

#pragma unroll
        for (int ks = 0; ks < 2; ks++) {
            int ku = ks * 8;
            uint32_t a[IM][4], b[8][2];
#pragma unroll
            for (int i = 0; i < IM; i++) {
                int mb = wm * (IM * 16) + i * 16 + gid;
                a[i][0] = sAu[mb * 20 + ku + tig];
                a[i][1] = sAu[(mb + 8) * 20 + ku + tig];
                a[i][2] = sAu[mb * 20 + ku + tig + 4];
                a[i][3] = sAu[(mb + 8) * 20 + ku + tig + 4];
            }
#pragma unroll
            for (int j = 0; j < 8; j++) {
                int nb = wn * 64 + j * 8 + gid;
                b[j][0] = sBu[nb * 20 + ku + tig];
                b[j][1] = sBu[nb * 20 + ku + tig + 4];
            }
#pragma unroll
            for (int i = 0; i < IM; i++)
#pragma unroll
                for (int j = 0; j < 8; j++) {
                    asm volatile(
                        "mma.sync.aligned.m16n8k16.row.col.f32.f16.f16.f32 "
                        "{%0,%1,%2,%3}, {%4,%5,%6,%7}, {%8,%9}, {%0,%1,%2,%3};"
                        : "+f"(c[i][j][0]), "+f"(c[i][j][1]),
                          "+f"(c[i][j][2]), "+f"(c[i][j][3])
                        : "r"(a[i][0]), "r"(a[i][1]), "r"(a[i][2]), "r"(a[i][3]),
                          "r"(b[j][0]), "r"(b[j][1]));
                }
        }
    }

    // ---- epilogue ----
#pragma unroll
    for (int i = 0; i < IM; i++) {
        int r0 = m0 + wm * (IM * 16) + i * 16 + gid;
#pragma unroll
        for (int j = 0; j < 8; j++) {
            int c0 = n0 + wn * 64 + j * 8 + 2 * tig;
#pragma unroll
            for (int rr = 0; rr < 2; rr++) {
                int gm = r0 + rr * 8;
                if (gm >= M) continue;
#pragma unroll
                for (int cc = 0; cc < 2; cc++) {
                    int gn = c0 + cc;
                    if (gn >= N) continue;
                    float v = c[i][j][rr * 2 + cc];
                    if (bias) v += bias[gn];
                    if (relu) v = fmaxf(v, 0.f);
                    if (C) C[(long long)gm * ldc + gn] = v;
                    if (Ch) {
                        int col = gn;
                        if (qkvpad) {
                            int seg = (gn >= 2 * DD) ? 2 : (gn >= DD ? 1 : 0);
                            col = seg * DP + (gn - seg * DD);
                        }
                        Ch[(long long)gm * ldh + col] = __float2half_rn(v);
                    }
                }
            }
        }
    }
}

template <int IM>
__global__ __launch_bounds__(256, 2)
void hgemm(int M, int N, int K,
           const __half* __restrict__ A, long long lda, long long sA,
           const __half* __restrict__ B, long long ldb, long long sB,
           float* __restrict__ C, long long ldc, long long sC,
           __half* __restrict__ Ch, long long ldh, long long sCh,
           const float* __restrict__ bias, long long sBias,
           int relu, int qkvpad) {
    extern __shared__ uint32_t dsm[];
    int z = blockIdx.z;
    A += (long long)z * sA;
    B += (long long)z * sB;
    if (C) C += (long long)z * sC;
    if (Ch) Ch += (long long)z * sCh;
    if (bias) bias += (long long)z * sBias;
    hg_core<IM>(M, N, K, A, lda, B, ldb, C, ldc, Ch, ldh, bias,
                relu, qkvpad, blockIdx.y * (IM * 64), blockIdx.x * 128, dsm);
}

// ---- dual fp16 GEMM (S0 || VoT), IM=1, z selects ----
struct HG {
    const __half* A; const __half* B; float* C; __half* Ch;
    long long lda, ldb, ldc, ldh;
    int M, N, K;
};

__global__ __launch_bounds__(256, 2)
void hg_dual(HG a0, HG a1) {
    extern __shared__ uint32_t dsm[];
    const HG& g = (blockIdx.z == 0) ? a0 : a1;
    hg_core<1>(g.M, g.N, g.K, g.A, g.lda, g.B, g.ldb, g.C, g.ldc,
               g.Ch, g.ldh, nullptr, 0, 0,
               blockIdx.y * 64, blockIdx.x * 128, dsm);
}

// ================= thin GEMM body (M == 14, fp32) =================
__device__ __forceinline__ void thin_body(
    int bid, int N, int K,
    const float* __restrict__ A, long long lda,
    const float* __restrict__ B, long long ldb,
    float* __restrict__ C, long long ldc,
    const float* __restrict__ bias, float* sAm) {
    int tid = threadIdx.x;
    int K4 = K >> 2;
    for (int idx = tid; idx < NN * K4; idx += 256) {
        int m = idx / K4, k4 = idx - m * K4;
        *(float4*)&sAm[m * 816 + k4 * 4] =
            *(const float4*)(A + (long long)m * lda + k4 * 4);
    }
    __syncthreads();

    int n = bid * 8 + (tid >> 5);
    int lane = tid & 31;
    float acc[NN];
#pragma unroll
    for (int m = 0; m < NN; m++) acc[m] = 0.f;

    if (n < N) {
        const float* Bp = B + (long long)n * ldb;
        for (int k = lane * 4; k + 4 <= K; k += 128) {
            float4 bv = *(const float4*)(Bp + k);
#pragma unroll
            for (int m = 0; m < NN; m++) {
                float4 av = *(const float4*)&sAm[m * 816 + k];
                acc[m] += av.x * bv.x + av.y * bv.y + av.z * bv.z + av.w * bv.w;
            }
        }
    }
#pragma unroll
    for (int off = 16; off; off >>= 1)
#pragma unroll
        for (int m = 0; m < NN; m++)
            acc[m] += __shfl_down_sync(0xffffffffu, acc[m], off);

    if (lane == 0 && n < N) {
        float bz = bias ? bias[n] : 0.f;
#pragma unroll
        for (int m = 0; m < NN; m++)
            C[(long long)m * ldc + n] = acc[m] + bz;
    }
}

// ---- prep: fp16 converts (3 segs) + qkvt thin + edge_prep(+cmean) ----
struct CSeg { const float* src; __half* dst; int scols, ccols, dld; long long total; };
struct PrepArgs {
    CSeg s[3];
    int nb[3];
    const float* we; const float* inw; const float* inb; float* qkvt;
    const int* ei;
};

__global__ __launch_bounds__(256)
void prep_kernel(PrepArgs pa) {
    __shared__ float sAm[NN * 816];
    int bid = blockIdx.x;
#pragma unroll
    for (int k = 0; k < 3; k++) {
        if (bid < pa.nb[k]) {
            const CSeg& s = pa.s[k];
            long long base = (long long)bid * 1024 + threadIdx.x * 4;
#pragma unroll
            for (int e = 0; e < 4; e++) {
                long long i = base + e;
                if (i < s.total) {
                    int r = (int)(i / s.ccols), c = (int)(i % s.ccols);
                    s.dst[(long long)r * s.dld + c] =
                        __float2half_rn(s.src[(long long)r * s.scols + c]);
                }
            }
            return;
        }
        bid -= pa.nb[k];
    }
    const int NB_QKVT = (D3 + 7) / 8;
    if (bid < NB_QKVT) {
        thin_body(bid, D3, TXT, pa.we, TXT, pa.inw + IMG, DD,
                  pa.qkvt, D3, pa.inb, sAm);
        return;
    }
    if (threadIdx.x != 0) return;
    const int* ei = pa.ei;
    float deg[NN]; int cnt[NN];
    for (int n = 0; n < NN; n++) { deg[n] = 0.f; cnt[n] = 0; }
    for (int e = 0; e < EE; e++) { int d = ei[EE + e]; deg[d] += 1.f; cnt[d]++; }
    for (int n = 0; n < NN; n++) { deg[n] += 1.f; cnt[n]++; }
    float dinv[NN];
    for (int n = 0; n < NN; n++) dinv[n] = (deg[n] > 0.f) ? rsqrtf(deg[n]) : 0.f;
    int off = 0, pos[NN];
    for (int n = 0; n < NN; n++) { g_eoff[n] = off; pos[n] = off; off += cnt[n]; }
    g_eoff[NN] = off;
    for (int e = 0; e < EE; e++) {
        int d = ei[EE + e], s = ei[e];
        int p = pos[d]++;
        g_esrc[p] = s;
        g_ewt[p]  = dinv[s] * dinv[d];
    }
    for (int n = 0; n < NN; n++) {
        int p = pos[n]++;
        g_esrc[p] = n;
        g_ewt[p]  = dinv[n] * dinv[n];
    }
    // cmean[src] = (1/NN) * sum over all Ahat entries with that source
    float cm[NN];
    for (int n = 0; n < NN; n++) cm[n] = 0.f;
    for (int e = 0; e < EE + NN; e++) cm[g_esrc[e]] += g_ewt[e];
    for (int n = 0; n < NN; n++) g_cmean[n] = cm[n] / (float)NN;
}

// ---- fused transpose+fp16 multi (3 segments) ----
struct TSeg { const float* src; __half* dst; int R, C, dld, nbx, nby; };
struct TTab { TSeg s[3]; int nb[3]; };

__global__ void transpose_multi(TTab tt) {
    __shared__ float t[32][33];
    int bid = blockIdx.x;
    int seg = 0;
#pragma unroll
    for (int k = 0; k < 3; k++) {
        if (bid < tt.nb[k]) { seg = k; break; }
        bid -= tt.nb[k];
    }
    const TSeg& s = tt.s[seg];
    int bx = bid % s.nbx, by = bid / s.nbx;
    int c0 = bx * 32, r0 = by * 32;
    int x = threadIdx.x, y = threadIdx.y;   // 32 x 8
#pragma unroll
    for (int j = 0; j < 4; j++) {
        int r = r0 + y + j * 8;
        if (r < s.R && c0 + x < s.C)
            t[y + j * 8][x] = s.src[(long long)r * s.C + c0 + x];
    }
    __syncthreads();
#pragma unroll
    for (int j = 0; j < 4; j++) {
        int c = c0 + y + j * 8;
        if (c < s.C && r0 + x < s.R)
            s.dst[(long long)c * s.dld + r0 + x] = __float2half_rn(t[x][y + j * 8]);
    }
}

// ---- fused thin pair: Bq + ovt ----
struct TPairArgs {
    int nb0;
    int N0, K0; const float* A0; long long lda0; const float* B0; long long ldb0;
    float* C0; long long ldc0; const float* bias0;
    int N1, K1; const float* A1; long long lda1; const float* B1; long long ldb1;
    float* C1; long long ldc1; const float* bias1;
};

__global__ __launch_bounds__(256)
void thin_pair(TPairArgs t) {
    __shared__ float sAm[NN * 816];
    int bid = blockIdx.x;
    if (bid < t.nb0)
        thin_body(bid, t.N0, t.K0, t.A0, t.lda0, t.B0, t.ldb0,
                  t.C0, t.ldc0, t.bias0, sAm);
    else
        thin_body(bid - t.nb0, t.N1, t.K1, t.A1, t.lda1, t.B1, t.ldb1,
                  t.C1, t.ldc1, t.bias1, sAm);
}

// ---------------- fp32 tiled SGEMM (small layers) ----------------
__global__ __launch_bounds__(256)
void sgemm_nt(int M, int N, int K,
              const float* __restrict__ A, long long lda,
              const float* __restrict__ B, long long ldb,
              float* __restrict__ C, long long ldc,
              const float* __restrict__ bias, int relu) {
    const int BM = 128, BN = 128, BK = 8;
    __shared__ float As[BK][BM];
    __shared__ float Bs[BK][BN];

    int m0 = blockIdx.y * BM;
    int n0 = blockIdx.x * BN;
    int tid = threadIdx.x;
    int tx = tid & 15, ty = tid >> 4;
    int arow = tid >> 1, acol = (tid & 1) * 4;
    int bnrow = tid >> 5, bncol = (tid & 31) * 4;

    float acc[8][8];
#pragma unroll
    for (int i = 0; i < 8; i++)
#pragma unroll
        for (int j = 0; j < 8; j++) acc[i][j] = 0.f;

    for (int k0 = 0; k0 < K; k0 += BK) {
        {
            int gm = m0 + arow, gk = k0 + acol;
            float4 v = make_float4(0.f, 0.f, 0.f, 0.f);
            if (gm < M && gk < K) {
                const float* p = A + (long long)gm * lda + gk;
                float t[4] = {0.f, 0.f, 0.f, 0.f};
#pragma unroll
                for (int i = 0; i < 4; i++) if (gk + i < K) t[i] = p[i];
                v = make_float4(t[0], t[1], t[2], t[3]);
            }
            As[acol + 0][arow] = v.x; As[acol + 1][arow] = v.y;
            As[acol + 2][arow] = v.z; As[acol + 3][arow] = v.w;
        }
        {
            int gk = k0 + bnrow, gj = n0 + bncol;
            float4 v = make_float4(0.f, 0.f, 0.f, 0.f);
            if (gk < K) {
                const float* p = B + (long long)gk * ldb + gj;
                float t[4] = {0.f, 0.f, 0.f, 0.f};
#pragma unroll
                for (int i = 0; i < 4; i++) if (gj + i < N) t[i] = p[i];
                v = make_float4(t[0], t[1], t[2], t[3]);
            }
            *(float4*)&Bs[bnrow][bncol] = v;
        }
        __syncthreads();

#pragma unroll
        for (int kk = 0; kk < BK; kk++) {
            float a[8], b[8];
#pragma unroll
            for (int i = 0; i < 8; i++) a[i] = As[kk][ty * 8 + i];
#pragma unroll
            for (int j = 0; j < 8; j++) b[j] = Bs[kk][tx * 8 + j];
#pragma unroll
            for (int i = 0; i < 8; i++)
#pragma unroll
                for (int j = 0; j < 8; j++) acc[i][j] = fmaf(a[i], b[j], acc[i][j]);
        }
        __syncthreads();
    }

#pragma unroll
    for (int i = 0; i < 8; i++) {
        int gm = m0 + ty * 8 + i;
        if (gm >= M) continue;
#pragma unroll
        for (int j = 0; j < 8; j++) {
            int gn = n0 + tx * 8 + j;
            if (gn >= N) continue;
            float v = acc[i][j];
            if (bias) v += bias[gn];
            if (relu) v = fmaxf(v, 0.f);
            C[(long long)gm * ldc + gn] = v;
        }
    }
}

// ------- fused softmax (fp16 store) ---
__global__ void softmax_fused(const float* __restrict__ S0,
                              const float* __restrict__ Bq,
                              __half* __restrict__ attn, float scale) {
    int l = blockIdx.x;
    int n = blockIdx.y;
    const float* s0 = S0 + (long long)l * BB;
    const float* bq = Bq + (long long)n * BB;
    __half* out = attn + ((long long)n * BB + l) * BB;

    int t = threadIdx.x;
    float v[4];
#pragma unroll
    for (int i = 0; i < 4; i++) {
        int m = t + i * 256;
        v[i] = scale * (s0[m] + bq[m]);
    }

    float mx = fmaxf(fmaxf(v[0], v[1]), fmaxf(v[2], v[3]));
#pragma unroll
    for (int o = 16; o; o >>= 1) mx = fmaxf(mx, __shfl_xor_sync(0xffffffffu, mx, o));
    __shared__ float sm[8];
    int lane = t & 31, wid = t >> 5;
    if (!lane) sm[wid] = mx;
    __syncthreads();
    if (t == 0) {
        float m = sm[0];
        for (int i = 1; i < 8; i++) m = fmaxf(m, sm[i]);
        sm[0] = m;
    }
    __syncthreads();
    mx = sm[0];

    float s = 0.f;
#pragma unroll
    for (int i = 0; i < 4; i++) { v[i] = __expf(v[i] - mx); s += v[i]; }
#pragma unroll
    for (int o = 16; o; o >>= 1) s += __shfl_xor_sync(0xffffffffu, s, o);
    __syncthreads();
    if (!lane) sm[wid] = s;
    __syncthreads();
    if (t == 0) {
        float a = 0.f;
        for (int i = 0; i < 8; i++) a += sm[i];
        sm[0] = a;
    }
    __syncthreads();
    float inv = 1.f / sm[0];
#pragma unroll
    for (int i = 0; i < 4; i++)
        out[t + i * 256] = __float2half_rn(v[i] * inv);
}

// -------- LN1: x1 = LN(node + ao2); fp32 + fp16 copies -----------
__global__ void ln1_kernel(const float* __restrict__ img, const float* __restrict__ we,
                           const float* __restrict__ R,
                           const float* __restrict__ g, const float* __restrict__ bb,
                           float* __restrict__ out, __half* __restrict__ outh) {
    const int D = DD;
    long long row = blockIdx.x;
    int b = (int)(row / NN);
    int n = (int)(row % NN);
    __shared__ float buf[DD];
    __shared__ float w1s[8], w2s[8];
    const float* ig = img + (long long)b * IMG;
    const float* w  = we + (long long)n * TXT;
    const float* r  = R + row * D;
    float s = 0.f, s2 = 0.f;
    for (int i = threadIdx.x; i < D; i += 256) {
        float nd = (i < IMG) ? ig[i] : w[i - IMG];
        float v = nd + r[i];
        buf[i] = v;
        s += v; s2 += v * v;
    }
#pragma unroll
    for (int o = 16; o; o >>= 1) {
        s  += __shfl_down_sync(0xffffffffu, s, o);
        s2 += __shfl_down_sync(0xffffffffu, s2, o);
    }
    int lane = threadIdx.x & 31, wid = threadIdx.x >> 5;
    if (!lane) { w1s[wid] = s; w2s[wid] = s2; }
    __syncthreads();
    if (threadIdx.x == 0) {
        float a = 0.f, b2 = 0.f;
        for (int i = 0; i < 8; i++) { a += w1s[i]; b2 += w2s[i]; }
        w1s[0] = a; w2s[0] = b2;
    }
    __syncthreads();
    float mean = w1s[0] / D;
    float var  = w2s[0] / D - mean * mean;
    float inv  = rsqrtf(var + 1e-5f);
    float* o = out + row * D;
    __half* oh = outh + row * DP;
    for (int i = threadIdx.x; i < D; i += 256) {
        float v = (buf[i] - mean) * inv * g[i] + bb[i];
        o[i] = v;
        oh[i] = __float2half_rn(v);
    }
}

// ---------------- LN2: x2_h = fp16(LN(X + R)) ----------------
__global__ void ln_kernel(const float* __restrict__ X, const float* __restrict__ R,
                          const float* __restrict__ g, const float* __restrict__ bb,
                          __half* __restrict__ outh) {
    const int D = DD;
    long long row = blockIdx.x;
    __shared__ float buf[DD];
    __shared__ float w1s[8], w2s[8];
    const float* x = X + row * D;
    const float* r = R + row * D;
    float s = 0.f, s2 = 0.f;
    for (int i = threadIdx.x; i < D; i += 256) {
        float v = x[i] + r[i];
        buf[i] = v;
        s += v; s2 += v * v;
    }
#pragma unroll
    for (int o = 16; o; o >>= 1) {
        s  += __shfl_down_sync(0xffffffffu, s, o);
        s2 += __shfl_down_sync(0xffffffffu, s2, o);
    }
    int lane = threadIdx.x & 31, wid = threadIdx.x >> 5;
    if (!lane) { w1s[wid] = s; w2s[wid] = s2; }
    __syncthreads();
    if (threadIdx.x == 0) {
        float a = 0.f, b2 = 0.f;
        for (int i = 0; i < 8; i++) { a += w1s[i]; b2 += w2s[i]; }
        w1s[0] = a; w2s[0] = b2;
    }
    __syncthreads();
    float mean = w1s[0] / D;
    float var  = w2s[0] / D - mean * mean;
    float inv  = rsqrtf(var + 1e-5f);
    __half* oh = outh + row * DP;
    for (int i = threadIdx.x; i < D; i += 256)
        oh[i] = __float2half_rn((buf[i] - mean) * inv * g[i] + bb[i]);
}

// ------ GCN: gsum[b][h] = sum_dst cmean[dst] * relu(agg(g1)[b,dst,h]+gb1[h]) -
__global__ __launch_bounds__(HID)
void gcn_gsum(const float* __restrict__ g1, const float* __restrict__ gb1,
              float* __restrict__ gsum) {
    __shared__ float sg[NN][HID];
    int b = blockIdx.x;
    int h = threadIdx.x;
    const float* base = g1 + (long long)b * NN * HID;
#pragma unroll
    for (int n = 0; n < NN; n++) sg[n][h] = base[n * HID + h];
    // each thread reads only column h (which it wrote) -> no sync needed
    float bz = gb1[h];
    float acc = 0.f;
#pragma unroll
    for (int dst = 0; dst < NN; dst++) {
        float a = bz;
        int e0 = g_eoff[dst], e1 = g_eoff[dst + 1];
        for (int e = e0; e < e1; e++)
            a += g_ewt[e] * sg[g_esrc[e]][h];
        a = fmaxf(a, 0.f);
        acc += g_cmean[dst] * a;
    }
    gsum[(long long)b * HID + h] = acc;
}

// ---------------- launch ----------------
static inline int ceil_div(int a, int b) { return (a + b - 1) / b; }

extern "C" void kernel_launch(void* const* d_in, const int* in_sizes, int n_in,
                              void* d_out, int out_size) {
    const float* img   = (const float*)d_in[0];
    const float* we    = (const float*)d_in[1];
    const int*   ei    = (const int*)  d_in[2];
    const float* inw   = (const float*)d_in[3];
    const float* inb   = (const float*)d_in[4];
    const float* outw  = (const float*)d_in[5];
    const float* outb  = (const float*)d_in[6];
    const float* ln1g  = (const float*)d_in[7];
    const float* ln1b  = (const float*)d_in[8];
    const float* ln2g  = (const float*)d_in[9];
    const float* ln2b  = (const float*)d_in[10];
    const float* w1    = (const float*)d_in[11];
    const float* b1    = (const float*)d_in[12];
    const float* w2    = (const float*)d_in[13];
    const float* b2    = (const float*)d_in[14];
    const float* gw1   = (const float*)d_in[15];
    const float* gb1   = (const float*)d_in[16];
    const float* gw2   = (const float*)d_in[17];
    const float* gb2   = (const float*)d_in[18];
    const float* lw    = (const float*)d_in[19];
    const float* lb    = (const float*)d_in[20];
    float* out = (float*)d_out;

    float *qkvi, *qkvt, *S0, *Bq, *ovt, *ao2, *x1, *ff, *g1, *gsum, *pool;
    __half *imgr_h, *inwr_h, *outwr_h, *qkvi_h, *VoT_h, *attn_h, *x1r_h;
    __half *w1t_h, *hid_h, *w2t_h, *x2_h, *gw1t_h;
    cudaGetSymbolAddress((void**)&qkvi, g_qkvi);
    cudaGetSymbolAddress((void**)&qkvt, g_qkvt);
    cudaGetSymbolAddress((void**)&S0,   g_S0);
    cudaGetSymbolAddress((void**)&Bq,   g_Bq);
    cudaGetSymbolAddress((void**)&ovt,  g_ovt);
    cudaGetSymbolAddress((void**)&ao2,  g_ao2);
    cudaGetSymbolAddress((void**)&x1,   g_x1);
    cudaGetSymbolAddress((void**)&ff,   g_ff);
    cudaGetSymbolAddress((void**)&g1,   g_g1);
    cudaGetSymbolAddress((void**)&gsum, g_gsum);
    cudaGetSymbolAddress((void**)&pool, g_pool);
    cudaGetSymbolAddress((void**)&imgr_h,  g_imgr_h);
    cudaGetSymbolAddress((void**)&inwr_h,  g_inwr_h);
    cudaGetSymbolAddress((void**)&outwr_h, g_outwr_h);
    cudaGetSymbolAddress((void**)&qkvi_h,  g_qkvi_h);
    cudaGetSymbolAddress((void**)&VoT_h,   g_VoT_h);
    cudaGetSymbolAddress((void**)&attn_h,  g_attn_h);
    cudaGetSymbolAddress((void**)&x1r_h,   g_x1r_h);
    cudaGetSymbolAddress((void**)&w1t_h,   g_w1t_h);
    cudaGetSymbolAddress((void**)&hid_h,   g_hid_h);
    cudaGetSymbolAddress((void**)&w2t_h,   g_w2t_h);
    cudaGetSymbolAddress((void**)&x2_h,    g_x2_h);
    cudaGetSymbolAddress((void**)&gw1t_h,  g_gw1t_h);

    cudaFuncSetAttribute(hgemm<2>,
                         cudaFuncAttributeMaxDynamicSharedMemorySize, CAC<2>::SMEM);
    cudaFuncSetAttribute(hgemm<1>,
                         cudaFuncAttributeMaxDynamicSharedMemorySize, CAC<1>::SMEM);
    cudaFuncSetAttribute(hg_dual,
                         cudaFuncAttributeMaxDynamicSharedMemorySize, CAC<1>::SMEM);

    const float attn_scale = 1.0f / sqrtf((float)DD);

    // 0) PREP: fp16 converts + qkvt thin + edge_prep(+cmean)
    {
        PrepArgs pa;
        pa.s[0] = { img,  imgr_h,  IMG, IMG, IMG, (long long)BB * IMG };
        pa.s[1] = { inw,  inwr_h,  DD,  IMG, IMG, (long long)D3 * IMG };
        pa.s[2] = { outw, outwr_h, DD,  DD,  DP,  (long long)DD * DD };
        int nblocks = 0;
        for (int k = 0; k < 3; k++) {
            pa.nb[k] = (int)((pa.s[k].total + 1023) / 1024);
            nblocks += pa.nb[k];
        }
        pa.we = we; pa.inw = inw; pa.inb = inb; pa.qkvt = qkvt; pa.ei = ei;
        nblocks += ceil_div(D3, 8) + 1;
        prep_kernel<<<nblocks, 256>>>(pa);
    }
    // 0b) transposed fp16 weights (one launch: w1, w2, gw1)
    {
        TTab tt;
        tt.s[0] = { w1,  w1t_h,  DD, FF,  DP, ceil_div(FF, 32),  ceil_div(DD, 32) };
        tt.s[1] = { w2,  w2t_h,  FF, DD,  FF, ceil_div(DD, 32),  ceil_div(FF, 32) };
        tt.s[2] = { gw1, gw1t_h, DD, HID, DP, ceil_div(HID, 32), ceil_div(DD, 32) };
        int nb = 0;
        for (int k = 0; k < 3; k++) {
            tt.nb[k] = tt.s[k].nbx * tt.s[k].nby;
            nb += tt.nb[k];
        }
        transpose_multi<<<nb, dim3(32, 8)>>>(tt);
    }

    // 1) qkvi = img @ Win[:, :512]^T  -> fp32 qkvi + padded fp16 qkvi_h
    hgemm<2><<<dim3(ceil_div(D3, 128), 8, 1), 256, CAC<2>::SMEM>>>(
        BB, D3, IMG, imgr_h, IMG, 0, inwr_h, IMG, 0,
        qkvi, D3, 0, qkvi_h, QLD, 0, nullptr, 0, 0, 1);

    // 2) DUAL: S0 = qi@ki^T (fp32) || VoT = Wout@vi^T (fp16)
    {
        HG a0, a1;
        a0.A = qkvi_h; a0.lda = QLD; a0.B = qkvi_h + DP; a0.ldb = QLD;
        a0.C = S0; a0.ldc = BB; a0.Ch = nullptr; a0.ldh = 0;
        a0.M = BB; a0.N = BB; a0.K = DD;
        a1.A = outwr_h; a1.lda = DP; a1.B = qkvi_h + 2 * DP; a1.ldb = QLD;
        a1.C = nullptr; a1.ldc = 0; a1.Ch = VoT_h; a1.ldh = BB;
        a1.M = DD; a1.N = BB; a1.K = DD;
        hg_dual<<<dim3(8, 16, 2), 256, CAC<1>::SMEM>>>(a0, a1);
    }

    // 3) DUAL thin: Bq || ovt (fp32)
    {
        TPairArgs tp;
        tp.nb0 = ceil_div(BB, 8);
        tp.N0 = BB; tp.K0 = DD; tp.A0 = qkvt; tp.lda0 = D3;
        tp.B0 = qkvi + DD; tp.ldb0 = D3; tp.C0 = Bq; tp.ldc0 = BB; tp.bias0 = nullptr;
        tp.N1 = DD; tp.K1 = DD; tp.A1 = qkvt + 2 * DD; tp.lda1 = D3;
        tp.B1 = outw; tp.ldb1 = DD; tp.C1 = ovt; tp.ldc1 = DD; tp.bias1 = outb;
        thin_pair<<<tp.nb0 + ceil_div(DD, 8), 256>>>(tp);
    }

    // 4) attn_h = fp16(softmax(scale*(S0 + Bq)))
    softmax_fused<<<dim3(BB, NN), 256>>>(S0, Bq, attn_h, attn_scale);

    // 5) ao2[l,n,:] = attn_n @ VoT^T + ovt[n]  (fp32 out, batched over n)
    hgemm<2><<<dim3(ceil_div(DD, 128), 8, NN), 256, CAC<2>::SMEM>>>(
        BB, DD, BB,
        attn_h, BB, (long long)BB * BB,
        VoT_h, BB, 0,
        ao2, (long long)NN * DD, DD,
        nullptr, 0, 0,
        ovt, DD, 0, 0);

    // 6) x1 = LN(node + ao2); x1r_h fp16
    ln1_kernel<<<MM, 256>>>(img, we, ao2, ln1g, ln1b, x1, x1r_h);

    // 7) hid_h = fp16(relu(x1r @ w1^T + b1))
    hgemm<2><<<dim3(ceil_div(FF, 128), ceil_div(MM, 128), 1), 256, CAC<2>::SMEM>>>(
        MM, FF, DD, x1r_h, DP, 0, w1t_h, DP, 0,
        nullptr, 0, 0, hid_h, FF, 0, b1, 0, 1, 0);

    // 8) ff = hid @ w2^T + b2 (fp32)
    hgemm<2><<<dim3(ceil_div(DD, 128), ceil_div(MM, 128), 1), 256, CAC<2>::SMEM>>>(
        MM, DD, FF, hid_h, FF, 0, w2t_h, FF, 0,
        ff, DD, 0, nullptr, 0, 0, b2, 0, 0, 0);

    // 9) x2_h = fp16(LN(x1 + ff))
    ln_kernel<<<MM, 256>>>(x1, ff, ln2g, ln2b, x2_h);

    // 10) g1 = x2 @ gw1^T (fp32)
    hgemm<1><<<dim3(1, ceil_div(MM, 64), 1), 256, CAC<1>::SMEM>>>(
        MM, HID, DD, x2_h, DP, 0, gw1t_h, DP, 0,
        g1, HID, 0, nullptr, 0, 0, nullptr, 0, 0, 0);

    // 11) gsum[b] = sum_n cmean[n]*relu(agg(g1)[b,n]+gb1)   (GCN tail collapse)
    gcn_gsum<<<BB, HID>>>(g1, gb1, gsum);

    // 12) pool = relu(gsum @ gw2 + gb2)   (mean-of-GCN2 == (c^T g2) @ gw2 + gb2)
    sgemm_nt<<<dim3(1, ceil_div(BB, 128), 1), 256>>>(
        BB, HID, HID, gsum, HID, gw2, HID, pool, HID, gb2, 1);

    // 13) out = pool @ lin_w + lin_b (fp32)
    sgemm_nt<<<dim3(1, ceil_div(BB, 128), 1), 256>>>(
        BB, CC, HID, pool, HID, lw, CC, out, CC, lb, 0);
}

// round 14
// speedup vs baseline: 1.1947x; 1.1947x over previous
#include <cuda_runtime.h>
#include <cuda_fp16.h>
#include <cstdint>
#include <math.h>

// ---------------- problem constants ----------------
#define BB   1024
#define IMG  512
#define TXT  300
#define NN   14
#define FF   2048
#define HID  128
#define CC   14
#define EE   182
#define DD   812     // IMG + TXT
#define D3   2436    // 3*D
#define MM   (BB*NN) // 14336 rows
#define DP   816     // DD padded to mult of 8
#define QLD  2448    // 3*DP, qkv fp16 row stride

// ---------------- fp32 scratch ----------------
__device__ float g_qkvi[(size_t)BB * D3];
__device__ float g_qkvt[(size_t)NN * D3];
__device__ float g_S0  [(size_t)BB * BB];
__device__ float g_Bq  [(size_t)NN * BB];
__device__ float g_ovt [(size_t)NN * DD];
__device__ float g_ao2 [(size_t)MM * DD];
__device__ float g_x1  [(size_t)MM * DD];
__device__ float g_ff  [(size_t)MM * DD];
__device__ float g_g1  [(size_t)MM * HID];
__device__ float g_gsum[(size_t)BB * HID];
__device__ float g_pool[(size_t)BB * HID];

// ---------------- fp16 scratch (tensor-core operands) ----------------
__device__ __align__(256) __half g_imgr_h [(size_t)BB * IMG];
__device__ __align__(256) __half g_inwr_h [(size_t)D3 * IMG];
__device__ __align__(256) __half g_outwr_h[(size_t)DD * DP];
__device__ __align__(256) __half g_qkvi_h [(size_t)BB * QLD];
__device__ __align__(256) __half g_VoT_h  [(size_t)DD * BB];
__device__ __align__(256) __half g_attn_h [(size_t)NN * BB * BB];
__device__ __align__(256) __half g_x1r_h  [(size_t)MM * DP];
__device__ __align__(256) __half g_w1t_h  [(size_t)FF * DP];
__device__ __align__(256) __half g_hid_h  [(size_t)MM * FF];
__device__ __align__(256) __half g_w2t_h  [(size_t)DD * FF];
__device__ __align__(256) __half g_x2_h   [(size_t)MM * DP];
__device__ __align__(256) __half g_gw1t_h [(size_t)HID * DP];

__device__ int   g_eoff[NN + 1];
__device__ int   g_esrc[EE + NN + 16];
__device__ float g_ewt [EE + NN + 16];
__device__ float g_cmean[NN];

// ========== fp16 mma.sync GEMM (cp.async, 3-stage, BT, K-chunk=KH) ==========
// C[m,n] = sum_k A[m,k]*B[n,k] (+bias, relu).  A/B fp16, K-major, 16B-aligned.
// CTA tile (IM*64)x128, 256 threads, 8 warps (4x2), warp tile (IM*16)x64.
// smem rows: RS u32 (KH/2 data + 4 pad), conflict-free for frag loads.
#define CA_STAGES 3
template <int IM, int KH> struct CAC {
    static const int RS = KH / 2 + 4;
    static const int A_U32 = IM * 64 * RS;
    static const int STAGE_U32 = A_U32 + 128 * RS;
    static const int SMEM = CA_STAGES * STAGE_U32 * 4;
};

template <int IM, int KH>
__device__ __forceinline__ void hfetch(
    int k0, int M, int N, int K,
    const __half* __restrict__ A, long long lda,
    const __half* __restrict__ B, long long ldb,
    int m0, int n0, int tid, uint32_t sA, uint32_t sB) {
    const int RS = CAC<IM, KH>::RS;
    const int CPR = KH / 8;                 // 16B chunks per row
    // ---- A: IM*64 rows ----
    {
        const int TOT = IM * 64 * CPR;
#pragma unroll
        for (int c = 0; c < TOT / 256; c++) {
            int idx = c * 256 + tid;
            int row = idx / CPR, ch = idx - row * CPR;
            int gm = m0 + row;
            bool mv = gm < M;
            const __half* rp = A + (long long)(mv ? gm : m0) * lda;
            int kh = k0 + ch * 8;
            int rem = K - kh;
            int vb = mv ? (rem >= 8 ? 16 : (rem > 0 ? rem * 2 : 0)) : 0;
            const __half* src = rp + (kh < K ? kh : 0);
            uint32_t dst = sA + (uint32_t)(row * RS + ch * 4) * 4u;
            asm volatile("cp.async.cg.shared.global [%0], [%1], 16, %2;"
                         :: "r"(dst), "l"(src), "r"(vb));
        }
    }
    // ---- B: 128 rows ----
    {
        const int TOT = 128 * CPR;
#pragma unroll
        for (int c = 0; c < TOT / 256; c++) {
            int idx = c * 256 + tid;
            int row = idx / CPR, ch = idx - row * CPR;
            int gj = n0 + row;
            bool nv = gj < N;
            const __half* rp = B + (long long)(nv ? gj : n0) * ldb;
            int kh = k0 + ch * 8;
            int rem = K - kh;
            int vb = nv ? (rem >= 8 ? 16 : (rem > 0 ? rem * 2 : 0)) : 0;
            const __half* src = rp + (kh < K ? kh : 0);
            uint32_t dst = sB + (uint32_t)(row * RS + ch * 4) * 4u;
            asm volatile("cp.async.cg.shared.global [%0], [%1], 16, %2;"
                         :: "r"(dst), "l"(src), "r"(vb));
        }
    }
}

template <int IM, int KH>
__device__ __forceinline__ void hg_core(
    int M, int N, int K,
    const __half* __restrict__ A, long long lda,
    const __half* __restrict__ B, long long ldb,
    float* __restrict__ C, long long ldc,
    __half* __restrict__ Ch, long long ldh,
    const float* __restrict__ bias,
    int relu, int qkvpad,
    int m0, int n0, uint32_t* dsm) {
    if (m0 >= M) return;
    const int RS = CAC<IM, KH>::RS;
    int tid = threadIdx.x;
    int warp = tid >> 5, lane = tid & 31;
    int wm = warp >> 1, wn = warp & 1;
    int gid = lane >> 2, tig = lane & 3;

    uint32_t smem_base = (uint32_t)__cvta_generic_to_shared(dsm);

    float c[IM][8][4];
#pragma unroll
    for (int i = 0; i < IM; i++)
#pragma unroll
        for (int j = 0; j < 8; j++)
#pragma unroll
            for (int r = 0; r < 4; r++) c[i][j][r] = 0.f;

    int ntiles = (K + KH - 1) / KH;

#pragma unroll
    for (int t = 0; t < CA_STAGES - 1; t++) {
        if (t < ntiles) {
            uint32_t sa = smem_base + (uint32_t)(t * CAC<IM, KH>::STAGE_U32) * 4u;
            hfetch<IM, KH>(t * KH, M, N, K, A, lda, B, ldb, m0, n0, tid,
                           sa, sa + (uint32_t)CAC<IM, KH>::A_U32 * 4u);
        }
        asm volatile("cp.async.commit_group;");
    }

    for (int t = 0; t < ntiles; t++) {
        asm volatile("cp.async.wait_group %0;" :: "n"(CA_STAGES - 2));
        __syncthreads();

        int nf = t + CA_STAGES - 1;
        if (nf < ntiles) {
            uint32_t sa = smem_base +
                (uint32_t)((nf % CA_STAGES) * CAC<IM, KH>::STAGE_U32) * 4u;
            hfetch<IM, KH>(nf * KH, M, N, K, A, lda, B, ldb, m0, n0, tid,
                           sa, sa + (uint32_t)CAC<IM, KH>::A_U32 * 4u);
        }
        asm volatile("cp.async.commit_group;");

        const uint32_t* sAu = dsm + (t % CA_STAGES) * CAC<IM, KH>::STAGE_U32;
        const uint32_t* sBu = sAu + CAC<IM, KH>::A_U32;

#pragma unroll
        for (int ks = 0; ks < KH / 16; ks++) {
            int ku = ks * 8;
            uint32_t a[IM][4], b[8][2];
#pragma unroll
            for (int i = 0; i < IM; i++) {
                int mb = wm * (IM * 16) + i * 16 + gid;
                a[i][0] = sAu[mb * RS + ku + tig];
                a[i][1] = sAu[(mb + 8) * RS + ku + tig];
                a[i][2] = sAu[mb * RS + ku + tig + 4];
                a[i][3] = sAu[(mb + 8) * RS + ku + tig + 4];
            }
#pragma unroll
            for (int j = 0; j < 8; j++) {
                int nb = wn * 64 + j * 8 + gid;
                b[j][0] = sBu[nb * RS + ku + tig];
                b[j][1] = sBu[nb * RS + ku + tig + 4];
            }
#pragma unroll
            for (int i = 0; i < IM; i++)
#pragma unroll
                for (int j = 0; j < 8; j++) {
                    asm volatile(
                        "mma.sync.aligned.m16n8k16.row.col.f32.f16.f16.f32 "
                        "{%0,%1,%2,%3}, {%4,%5,%6,%7}, {%8,%9}, {%0,%1,%2,%3};"
                        : "+f"(c[i][j][0]), "+f"(c[i][j][1]),
                          "+f"(c[i][j][2]), "+f"(c[i][j][3])
                        : "r"(a[i][0]), "r"(a[i][1]), "r"(a[i][2]), "r"(a[i][3]),
                          "r"(b[j][0]), "r"(b[j][1]));
                }
        }
    }

    // ---- epilogue ----
#pragma unroll
    for (int i = 0; i < IM; i++) {
        int r0 = m0 + wm * (IM * 16) + i * 16 + gid;
#pragma unroll
        for (int j = 0; j < 8; j++) {
            int c0 = n0 + wn * 64 + j * 8 + 2 * tig;
#pragma unroll
            for (int rr = 0; rr < 2; rr++) {
                int gm = r0 + rr * 8;
                if (gm >= M) continue;
#pragma unroll
                for (int cc = 0; cc < 2; cc++) {
                    int gn = c0 + cc;
                    if (gn >= N) continue;
                    float v = c[i][j][rr * 2 + cc];
                    if (bias) v += bias[gn];
                    if (relu) v = fmaxf(v, 0.f);
                    if (C) C[(long long)gm * ldc + gn] = v;
                    if (Ch) {
                        int col = gn;
                        if (qkvpad) {
                            int seg = (gn >= 2 * DD) ? 2 : (gn >= DD ? 1 : 0);
                            col = seg * DP + (gn - seg * DD);
                        }
                        Ch[(long long)gm * ldh + col] = __float2half_rn(v);
                    }
                }
            }
        }
    }
}

template <int IM, int KH>
__global__ __launch_bounds__(256, 2)
void hgemm(int M, int N, int K,
           const __half* __restrict__ A, long long lda, long long sA,
           const __half* __restrict__ B, long long ldb, long long sB,
           float* __restrict__ C, long long ldc, long long sC,
           __half* __restrict__ Ch, long long ldh, long long sCh,
           const float* __restrict__ bias, long long sBias,
           int relu, int qkvpad) {
    extern __shared__ uint32_t dsm[];
    int z = blockIdx.z;
    A += (long long)z * sA;
    B += (long long)z * sB;
    if (C) C += (long long)z * sC;
    if (Ch) Ch += (long long)z * sCh;
    if (bias) bias += (long long)z * sBias;
    hg_core<IM, KH>(M, N, K, A, lda, B, ldb, C, ldc, Ch, ldh, bias,
                    relu, qkvpad, blockIdx.y * (IM * 64), blockIdx.x * 128, dsm);
}

// ---- dual fp16 GEMM (S0 || VoT), IM=1/KH=64, z selects ----
struct HG {
    const __half* A; const __half* B; float* C; __half* Ch;
    long long lda, ldb, ldc, ldh;
    int M, N, K;
};

__global__ __launch_bounds__(256, 2)
void hg_dual(HG a0, HG a1) {
    extern __shared__ uint32_t dsm[];
    const HG& g = (blockIdx.z == 0) ? a0 : a1;
    hg_core<1, 64>(g.M, g.N, g.K, g.A, g.lda, g.B, g.ldb, g.C, g.ldc,
                   g.Ch, g.ldh, nullptr, 0, 0,
                   blockIdx.y * 64, blockIdx.x * 128, dsm);
}

// ================= thin GEMM body (M == 14, fp32) =================
__device__ __forceinline__ void thin_body(
    int bid, int N, int K,
    const float* __restrict__ A, long long lda,
    const float* __restrict__ B, long long ldb,
    float* __restrict__ C, long long ldc,
    const float* __restrict__ bias, float* sAm) {
    int tid = threadIdx.x;
    int K4 = K >> 2;
    for (int idx = tid; idx < NN * K4; idx += 256) {
        int m = idx / K4, k4 = idx - m * K4;
        *(float4*)&sAm[m * 816 + k4 * 4] =
            *(const float4*)(A + (long long)m * lda + k4 * 4);
    }
    __syncthreads();

    int n = bid * 8 + (tid >> 5);
    int lane = tid & 31;
    float acc[NN];
#pragma unroll
    for (int m = 0; m < NN; m++) acc[m] = 0.f;

    if (n < N) {
        const float* Bp = B + (long long)n * ldb;
        for (int k = lane * 4; k + 4 <= K; k += 128) {
            float4 bv = *(const float4*)(Bp + k);
#pragma unroll
            for (int m = 0; m < NN; m++) {
                float4 av = *(const float4*)&sAm[m * 816 + k];
                acc[m] += av.x * bv.x + av.y * bv.y + av.z * bv.z + av.w * bv.w;
            }
        }
    }
#pragma unroll
    for (int off = 16; off; off >>= 1)
#pragma unroll
        for (int m = 0; m < NN; m++)
            acc[m] += __shfl_down_sync(0xffffffffu, acc[m], off);

    if (lane == 0 && n < N) {
        float bz = bias ? bias[n] : 0.f;
#pragma unroll
        for (int m = 0; m < NN; m++)
            C[(long long)m * ldc + n] = acc[m] + bz;
    }
}

// ---- prep: fp16 converts (3 segs) + qkvt thin + edge_prep(+cmean) ----
struct CSeg { const float* src; __half* dst; int scols, ccols, dld; long long total; };
struct PrepArgs {
    CSeg s[3];
    int nb[3];
    const float* we; const float* inw; const float* inb; float* qkvt;
    const int* ei;
};

__global__ __launch_bounds__(256)
void prep_kernel(PrepArgs pa) {
    __shared__ float sAm[NN * 816];
    int bid = blockIdx.x;
#pragma unroll
    for (int k = 0; k < 3; k++) {
        if (bid < pa.nb[k]) {
            const CSeg& s = pa.s[k];
            long long base = (long long)bid * 1024 + threadIdx.x * 4;
#pragma unroll
            for (int e = 0; e < 4; e++) {
                long long i = base + e;
                if (i < s.total) {
                    int r = (int)(i / s.ccols), c = (int)(i % s.ccols);
                    s.dst[(long long)r * s.dld + c] =
                        __float2half_rn(s.src[(long long)r * s.scols + c]);
                }
            }
            return;
        }
        bid -= pa.nb[k];
    }
    const int NB_QKVT = (D3 + 7) / 8;
    if (bid < NB_QKVT) {
        thin_body(bid, D3, TXT, pa.we, TXT, pa.inw + IMG, DD,
                  pa.qkvt, D3, pa.inb, sAm);
        return;
    }
    if (threadIdx.x != 0) return;
    const int* ei = pa.ei;
    float deg[NN]; int cnt[NN];
    for (int n = 0; n < NN; n++) { deg[n] = 0.f; cnt[n] = 0; }
    for (int e = 0; e < EE; e++) { int d = ei[EE + e]; deg[d] += 1.f; cnt[d]++; }
    for (int n = 0; n < NN; n++) { deg[n] += 1.f; cnt[n]++; }
    float dinv[NN];
    for (int n = 0; n < NN; n++) dinv[n] = (deg[n] > 0.f) ? rsqrtf(deg[n]) : 0.f;
    int off = 0, pos[NN];
    for (int n = 0; n < NN; n++) { g_eoff[n] = off; pos[n] = off; off += cnt[n]; }
    g_eoff[NN] = off;
    for (int e = 0; e < EE; e++) {
        int d = ei[EE + e], s = ei[e];
        int p = pos[d]++;
        g_esrc[p] = s;
        g_ewt[p]  = dinv[s] * dinv[d];
    }
    for (int n = 0; n < NN; n++) {
        int p = pos[n]++;
        g_esrc[p] = n;
        g_ewt[p]  = dinv[n] * dinv[n];
    }
    float cm[NN];
    for (int n = 0; n < NN; n++) cm[n] = 0.f;
    for (int e = 0; e < EE + NN; e++) cm[g_esrc[e]] += g_ewt[e];
    for (int n = 0; n < NN; n++) g_cmean[n] = cm[n] / (float)NN;
}

// ---- fused transpose+fp16 multi (3 segments) ----
struct TSeg { const float* src; __half* dst; int R, C, dld, nbx, nby; };
struct TTab { TSeg s[3]; int nb[3]; };

__global__ void transpose_multi(TTab tt) {
    __shared__ float t[32][33];
    int bid = blockIdx.x;
    int seg = 0;
#pragma unroll
    for (int k = 0; k < 3; k++) {
        if (bid < tt.nb[k]) { seg = k; break; }
        bid -= tt.nb[k];
    }
    const TSeg& s = tt.s[seg];
    int bx = bid % s.nbx, by = bid / s.nbx;
    int c0 = bx * 32, r0 = by * 32;
    int x = threadIdx.x, y = threadIdx.y;
#pragma unroll
    for (int j = 0; j < 4; j++) {
        int r = r0 + y + j * 8;
        if (r < s.R && c0 + x < s.C)
            t[y + j * 8][x] = s.src[(long long)r * s.C + c0 + x];
    }
    __syncthreads();
#pragma unroll
    for (int j = 0; j < 4; j++) {
        int c = c0 + y + j * 8;
        if (c < s.C && r0 + x < s.R)
            s.dst[(long long)c * s.dld + r0 + x] = __float2half_rn(t[x][y + j * 8]);
    }
}

// ---- fused thin pair: Bq + ovt ----
struct TPairArgs {
    int nb0;
    int N0, K0; const float* A0; long long lda0; const float* B0; long long ldb0;
    float* C0; long long ldc0; const float* bias0;
    int N1, K1; const float* A1; long long lda1; const float* B1; long long ldb1;
    float* C1; long long ldc1; const float* bias1;
};

__global__ __launch_bounds__(256)
void thin_pair(TPairArgs t) {
    __shared__ float sAm[NN * 816];
    int bid = blockIdx.x;
    if (bid < t.nb0)
        thin_body(bid, t.N0, t.K0, t.A0, t.lda0, t.B0, t.ldb0,
                  t.C0, t.ldc0, t.bias0, sAm);
    else
        thin_body(bid - t.nb0, t.N1, t.K1, t.A1, t.lda1, t.B1, t.ldb1,
                  t.C1, t.ldc1, t.bias1, sAm);
}

// ---------------- fp32 tiled SGEMM (small layers) ----------------
__global__ __launch_bounds__(256)
void sgemm_nt(int M, int N, int K,
              const float* __restrict__ A, long long lda,
              const float* __restrict__ B, long long ldb,
              float* __restrict__ C, long long ldc,
              const float* __restrict__ bias, int relu) {
    const int BM = 128, BN = 128, BK = 8;
    __shared__ float As[BK][BM];
    __shared__ float Bs[BK][BN];

    int m0 = blockIdx.y * BM;
    int n0 = blockIdx.x * BN;
    int tid = threadIdx.x;
    int tx = tid & 15, ty = tid >> 4;
    int arow = tid >> 1, acol = (tid & 1) * 4;
    int bnrow = tid >> 5, bncol = (tid & 31) * 4;

    float acc[8][8];
#pragma unroll
    for (int i = 0; i < 8; i++)
#pragma unroll
        for (int j = 0; j < 8; j++) acc[i][j] = 0.f;

    for (int k0 = 0; k0 < K; k0 += BK) {
        {
            int gm = m0 + arow, gk = k0 + acol;
            float4 v = make_float4(0.f, 0.f, 0.f, 0.f);
            if (gm < M && gk < K) {
                const float* p = A + (long long)gm * lda + gk;
                float t[4] = {0.f, 0.f, 0.f, 0.f};
#pragma unroll
                for (int i = 0; i < 4; i++) if (gk + i < K) t[i] = p[i];
                v = make_float4(t[0], t[1], t[2], t[3]);
            }
            As[acol + 0][arow] = v.x; As[acol + 1][arow] = v.y;
            As[acol + 2][arow] = v.z; As[acol + 3][arow] = v.w;
        }
        {
            int gk = k0 + bnrow, gj = n0 + bncol;
            float4 v = make_float4(0.f, 0.f, 0.f, 0.f);
            if (gk < K) {
                const float* p = B + (long long)gk * ldb + gj;
                float t[4] = {0.f, 0.f, 0.f, 0.f};
#pragma unroll
                for (int i = 0; i < 4; i++) if (gj + i < N) t[i] = p[i];
                v = make_float4(t[0], t[1], t[2], t[3]);
            }
            *(float4*)&Bs[bnrow][bncol] = v;
        }
        __syncthreads();

#pragma unroll
        for (int kk = 0; kk < BK; kk++) {
            float a[8], b[8];
#pragma unroll
            for (int i = 0; i < 8; i++) a[i] = As[kk][ty * 8 + i];
#pragma unroll
            for (int j = 0; j < 8; j++) b[j] = Bs[kk][tx * 8 + j];
#pragma unroll
            for (int i = 0; i < 8; i++)
#pragma unroll
                for (int j = 0; j < 8; j++) acc[i][j] = fmaf(a[i], b[j], acc[i][j]);
        }
        __syncthreads();
    }

#pragma unroll
    for (int i = 0; i < 8; i++) {
        int gm = m0 + ty * 8 + i;
        if (gm >= M) continue;
#pragma unroll
        for (int j = 0; j < 8; j++) {
            int gn = n0 + tx * 8 + j;
            if (gn >= N) continue;
            float v = acc[i][j];
            if (bias) v += bias[gn];
            if (relu) v = fmaxf(v, 0.f);
            C[(long long)gm * ldc + gn] = v;
        }
    }
}

// ------- fused softmax (fp16 store) ---
__global__ void softmax_fused(const float* __restrict__ S0,
                              const float* __restrict__ Bq,
                              __half* __restrict__ attn, float scale) {
    int l = blockIdx.x;
    int n = blockIdx.y;
    const float* s0 = S0 + (long long)l * BB;
    const float* bq = Bq + (long long)n * BB;
    __half* out = attn + ((long long)n * BB + l) * BB;

    int t = threadIdx.x;
    float v[4];
#pragma unroll
    for (int i = 0; i < 4; i++) {
        int m = t + i * 256;
        v[i] = scale * (s0[m] + bq[m]);
    }

    float mx = fmaxf(fmaxf(v[0], v[1]), fmaxf(v[2], v[3]));
#pragma unroll
    for (int o = 16; o; o >>= 1) mx = fmaxf(mx, __shfl_xor_sync(0xffffffffu, mx, o));
    __shared__ float sm[8];
    int lane = t & 31, wid = t >> 5;
    if (!lane) sm[wid] = mx;
    __syncthreads();
    if (t == 0) {
        float m = sm[0];
        for (int i = 1; i < 8; i++) m = fmaxf(m, sm[i]);
        sm[0] = m;
    }
    __syncthreads();
    mx = sm[0];

    float s = 0.f;
#pragma unroll
    for (int i = 0; i < 4; i++) { v[i] = __expf(v[i] - mx); s += v[i]; }
#pragma unroll
    for (int o = 16; o; o >>= 1) s += __shfl_xor_sync(0xffffffffu, s, o);
    __syncthreads();
    if (!lane) sm[wid] = s;
    __syncthreads();
    if (t == 0) {
        float a = 0.f;
        for (int i = 0; i < 8; i++) a += sm[i];
        sm[0] = a;
    }
    __syncthreads();
    float inv = 1.f / sm[0];
#pragma unroll
    for (int i = 0; i < 4; i++)
        out[t + i * 256] = __float2half_rn(v[i] * inv);
}

// -------- LN1: x1 = LN(node + ao2); fp32 + fp16 copies -----------
__global__ void ln1_kernel(const float* __restrict__ img, const float* __restrict__ we,
                           const float* __restrict__ R,
                           const float* __restrict__ g, const float* __restrict__ bb,
                           float* __restrict__ out, __half* __restrict__ outh) {
    const int D = DD;
    long long row = blockIdx.x;
    int b = (int)(row / NN);
    int n = (int)(row % NN);
    __shared__ float buf[DD];
    __shared__ float w1s[8], w2s[8];
    const float* ig = img + (long long)b * IMG;
    const float* w  = we + (long long)n * TXT;
    const float* r  = R + row * D;
    float s = 0.f, s2 = 0.f;
    for (int i = threadIdx.x; i < D; i += 256) {
        float nd = (i < IMG) ? ig[i] : w[i - IMG];
        float v = nd + r[i];
        buf[i] = v;
        s += v; s2 += v * v;
    }
#pragma unroll
    for (int o = 16; o; o >>= 1) {
        s  += __shfl_down_sync(0xffffffffu, s, o);
        s2 += __shfl_down_sync(0xffffffffu, s2, o);
    }
    int lane = threadIdx.x & 31, wid = threadIdx.x >> 5;
    if (!lane) { w1s[wid] = s; w2s[wid] = s2; }
    __syncthreads();
    if (threadIdx.x == 0) {
        float a = 0.f, b2 = 0.f;
        for (int i = 0; i < 8; i++) { a += w1s[i]; b2 += w2s[i]; }
        w1s[0] = a; w2s[0] = b2;
    }
    __syncthreads();
    float mean = w1s[0] / D;
    float var  = w2s[0] / D - mean * mean;
    float inv  = rsqrtf(var + 1e-5f);
    float* o = out + row * D;
    __half* oh = outh + row * DP;
    for (int i = threadIdx.x; i < D; i += 256) {
        float v = (buf[i] - mean) * inv * g[i] + bb[i];
        o[i] = v;
        oh[i] = __float2half_rn(v);
    }
}

// ---------------- LN2: x2_h = fp16(LN(X + R)) ----------------
__global__ void ln_kernel(const float* __restrict__ X, const float* __restrict__ R,
                          const float* __restrict__ g, const float* __restrict__ bb,
                          __half* __restrict__ outh) {
    const int D = DD;
    long long row = blockIdx.x;
    __shared__ float buf[DD];
    __shared__ float w1s[8], w2s[8];
    const float* x = X + row * D;
    const float* r = R + row * D;
    float s = 0.f, s2 = 0.f;
    for (int i = threadIdx.x; i < D; i += 256) {
        float v = x[i] + r[i];
        buf[i] = v;
        s += v; s2 += v * v;
    }
#pragma unroll
    for (int o = 16; o; o >>= 1) {
        s  += __shfl_down_sync(0xffffffffu, s, o);
        s2 += __shfl_down_sync(0xffffffffu, s2, o);
    }
    int lane = threadIdx.x & 31, wid = threadIdx.x >> 5;
    if (!lane) { w1s[wid] = s; w2s[wid] = s2; }
    __syncthreads();
    if (threadIdx.x == 0) {
        float a = 0.f, b2 = 0.f;
        for (int i = 0; i < 8; i++) { a += w1s[i]; b2 += w2s[i]; }
        w1s[0] = a; w2s[0] = b2;
    }
    __syncthreads();
    float mean = w1s[0] / D;
    float var  = w2s[0] / D - mean * mean;
    float inv  = rsqrtf(var + 1e-5f);
    __half* oh = outh + row * DP;
    for (int i = threadIdx.x; i < D; i += 256)
        oh[i] = __float2half_rn((buf[i] - mean) * inv * g[i] + bb[i]);
}

// ------ GCN tail: gsum[b][h] = sum_dst cmean[dst]*relu(agg(g1)[b,dst,h]+gb1[h])
__global__ __launch_bounds__(HID)
void gcn_gsum(const float* __restrict__ g1, const float* __restrict__ gb1,
              float* __restrict__ gsum) {
    __shared__ float sg[NN][HID];
    int b = blockIdx.x;
    int h = threadIdx.x;
    const float* base = g1 + (long long)b * NN * HID;
#pragma unroll
    for (int n = 0; n < NN; n++) sg[n][h] = base[n * HID + h];
    float bz = gb1[h];
    float acc = 0.f;
#pragma unroll
    for (int dst = 0; dst < NN; dst++) {
        float a = bz;
        int e0 = g_eoff[dst], e1 = g_eoff[dst + 1];
        for (int e = e0; e < e1; e++)
            a += g_ewt[e] * sg[g_esrc[e]][h];
        a = fmaxf(a, 0.f);
        acc += g_cmean[dst] * a;
    }
    gsum[(long long)b * HID + h] = acc;
}

// ---------------- launch ----------------
static inline int ceil_div(int a, int b) { return (a + b - 1) / b; }

extern "C" void kernel_launch(void* const* d_in, const int* in_sizes, int n_in,
                              void* d_out, int out_size) {
    const float* img   = (const float*)d_in[0];
    const float* we    = (const float*)d_in[1];
    const int*   ei    = (const int*)  d_in[2];
    const float* inw   = (const float*)d_in[3];
    const float* inb   = (const float*)d_in[4];
    const float* outw  = (const float*)d_in[5];
    const float* outb  = (const float*)d_in[6];
    const float* ln1g  = (const float*)d_in[7];
    const float* ln1b  = (const float*)d_in[8];
    const float* ln2g  = (const float*)d_in[9];
    const float* ln2b  = (const float*)d_in[10];
    const float* w1    = (const float*)d_in[11];
    const float* b1    = (const float*)d_in[12];
    const float* w2    = (const float*)d_in[13];
    const float* b2    = (const float*)d_in[14];
    const float* gw1   = (const float*)d_in[15];
    const float* gb1   = (const float*)d_in[16];
    const float* gw2   = (const float*)d_in[17];
    const float* gb2   = (const float*)d_in[18];
    const float* lw    = (const float*)d_in[19];
    const float* lb    = (const float*)d_in[20];
    float* out = (float*)d_out;

    float *qkvi, *qkvt, *S0, *Bq, *ovt, *ao2, *x1, *ff, *g1, *gsum, *pool;
    __half *imgr_h, *inwr_h, *outwr_h, *qkvi_h, *VoT_h, *attn_h, *x1r_h;
    __half *w1t_h, *hid_h, *w2t_h, *x2_h, *gw1t_h;
    cudaGetSymbolAddress((void**)&qkvi, g_qkvi);
    cudaGetSymbolAddress((void**)&qkvt, g_qkvt);
    cudaGetSymbolAddress((void**)&S0,   g_S0);
    cudaGetSymbolAddress((void**)&Bq,   g_Bq);
    cudaGetSymbolAddress((void**)&ovt,  g_ovt);
    cudaGetSymbolAddress((void**)&ao2,  g_ao2);
    cudaGetSymbolAddress((void**)&x1,   g_x1);
    cudaGetSymbolAddress((void**)&ff,   g_ff);
    cudaGetSymbolAddress((void**)&g1,   g_g1);
    cudaGetSymbolAddress((void**)&gsum, g_gsum);
    cudaGetSymbolAddress((void**)&pool, g_pool);
    cudaGetSymbolAddress((void**)&imgr_h,  g_imgr_h);
    cudaGetSymbolAddress((void**)&inwr_h,  g_inwr_h);
    cudaGetSymbolAddress((void**)&outwr_h, g_outwr_h);
    cudaGetSymbolAddress((void**)&qkvi_h,  g_qkvi_h);
    cudaGetSymbolAddress((void**)&VoT_h,   g_VoT_h);
    cudaGetSymbolAddress((void**)&attn_h,  g_attn_h);
    cudaGetSymbolAddress((void**)&x1r_h,   g_x1r_h);
    cudaGetSymbolAddress((void**)&w1t_h,   g_w1t_h);
    cudaGetSymbolAddress((void**)&hid_h,   g_hid_h);
    cudaGetSymbolAddress((void**)&w2t_h,   g_w2t_h);
    cudaGetSymbolAddress((void**)&x2_h,    g_x2_h);
    cudaGetSymbolAddress((void**)&gw1t_h,  g_gw1t_h);

    cudaFuncSetAttribute(hgemm<2, 64>,
                         cudaFuncAttributeMaxDynamicSharedMemorySize, CAC<2, 64>::SMEM);
    cudaFuncSetAttribute(hgemm<1, 64>,
                         cudaFuncAttributeMaxDynamicSharedMemorySize, CAC<1, 64>::SMEM);
    cudaFuncSetAttribute(hg_dual,
                         cudaFuncAttributeMaxDynamicSharedMemorySize, CAC<1, 64>::SMEM);

    const float attn_scale = 1.0f / sqrtf((float)DD);

    // 0) PREP: fp16 converts + qkvt thin + edge_prep(+cmean)
    {
        PrepArgs pa;
        pa.s[0] = { img,  imgr_h,  IMG, IMG, IMG, (long long)BB * IMG };
        pa.s[1] = { inw,  inwr_h,  DD,  IMG, IMG, (long long)D3 * IMG };
        pa.s[2] = { outw, outwr_h, DD,  DD,  DP,  (long long)DD * DD };
        int nblocks = 0;
        for (int k = 0; k < 3; k++) {
            pa.nb[k] = (int)((pa.s[k].total + 1023) / 1024);
            nblocks += pa.nb[k];
        }
        pa.we = we; pa.inw = inw; pa.inb = inb; pa.qkvt = qkvt; pa.ei = ei;
        nblocks += ceil_div(D3, 8) + 1;
        prep_kernel<<<nblocks, 256>>>(pa);
    }
    // 0b) transposed fp16 weights (one launch: w1, w2, gw1)
    {
        TTab tt;
        tt.s[0] = { w1,  w1t_h,  DD, FF,  DP, ceil_div(FF, 32),  ceil_div(DD, 32) };
        tt.s[1] = { w2,  w2t_h,  FF, DD,  FF, ceil_div(DD, 32),  ceil_div(FF, 32) };
        tt.s[2] = { gw1, gw1t_h, DD, HID, DP, ceil_div(HID, 32), ceil_div(DD, 32) };
        int nb = 0;
        for (int k = 0; k < 3; k++) {
            tt.nb[k] = tt.s[k].nbx * tt.s[k].nby;
            nb += tt.nb[k];
        }
        transpose_multi<<<nb, dim3(32, 8)>>>(tt);
    }

    // 1) qkvi = img @ Win[:, :512]^T  -> fp32 qkvi + padded fp16 qkvi_h
    hgemm<2, 64><<<dim3(ceil_div(D3, 128), 8, 1), 256, CAC<2, 64>::SMEM>>>(
        BB, D3, IMG, imgr_h, IMG, 0, inwr_h, IMG, 0,
        qkvi, D3, 0, qkvi_h, QLD, 0, nullptr, 0, 0, 1);

    // 2) DUAL: S0 = qi@ki^T (fp32) || VoT = Wout@vi^T (fp16)
    {
        HG a0, a1;
        a0.A = qkvi_h; a0.lda = QLD; a0.B = qkvi_h + DP; a0.ldb = QLD;
        a0.C = S0; a0.ldc = BB; a0.Ch = nullptr; a0.ldh = 0;
        a0.M = BB; a0.N = BB; a0.K = DD;
        a1.A = outwr_h; a1.lda = DP; a1.B = qkvi_h + 2 * DP; a1.ldb = QLD;
        a1.C = nullptr; a1.ldc = 0; a1.Ch = VoT_h; a1.ldh = BB;
        a1.M = DD; a1.N = BB; a1.K = DD;
        hg_dual<<<dim3(8, 16, 2), 256, CAC<1, 64>::SMEM>>>(a0, a1);
    }

    // 3) DUAL thin: Bq || ovt (fp32)
    {
        TPairArgs tp;
        tp.nb0 = ceil_div(BB, 8);
        tp.N0 = BB; tp.K0 = DD; tp.A0 = qkvt; tp.lda0 = D3;
        tp.B0 = qkvi + DD; tp.ldb0 = D3; tp.C0 = Bq; tp.ldc0 = BB; tp.bias0 = nullptr;
        tp.N1 = DD; tp.K1 = DD; tp.A1 = qkvt + 2 * DD; tp.lda1 = D3;
        tp.B1 = outw; tp.ldb1 = DD; tp.C1 = ovt; tp.ldc1 = DD; tp.bias1 = outb;
        thin_pair<<<tp.nb0 + ceil_div(DD, 8), 256>>>(tp);
    }

    // 4) attn_h = fp16(softmax(scale*(S0 + Bq)))
    softmax_fused<<<dim3(BB, NN), 256>>>(S0, Bq, attn_h, attn_scale);

    // 5) ao2[l,n,:] = attn_n @ VoT^T + ovt[n]  (fp32 out, batched over n)
    hgemm<2, 64><<<dim3(ceil_div(DD, 128), 8, NN), 256, CAC<2, 64>::SMEM>>>(
        BB, DD, BB,
        attn_h, BB, (long long)BB * BB,
        VoT_h, BB, 0,
        ao2, (long long)NN * DD, DD,
        nullptr, 0, 0,
        ovt, DD, 0, 0);

    // 6) x1 = LN(node + ao2); x1r_h fp16
    ln1_kernel<<<MM, 256>>>(img, we, ao2, ln1g, ln1b, x1, x1r_h);

    // 7) hid_h = fp16(relu(x1r @ w1^T + b1))
    hgemm<2, 64><<<dim3(ceil_div(FF, 128), ceil_div(MM, 128), 1), 256, CAC<2, 64>::SMEM>>>(
        MM, FF, DD, x1r_h, DP, 0, w1t_h, DP, 0,
        nullptr, 0, 0, hid_h, FF, 0, b1, 0, 1, 0);

    // 8) ff = hid @ w2^T + b2 (fp32)
    hgemm<2, 64><<<dim3(ceil_div(DD, 128), ceil_div(MM, 128), 1), 256, CAC<2, 64>::SMEM>>>(
        MM, DD, FF, hid_h, FF, 0, w2t_h, FF, 0,
        ff, DD, 0, nullptr, 0, 0, b2, 0, 0, 0);

    // 9) x2_h = fp16(LN(x1 + ff))
    ln_kernel<<<MM, 256>>>(x1, ff, ln2g, ln2b, x2_h);

    // 10) g1 = x2 @ gw1^T (fp32)
    hgemm<1, 64><<<dim3(1, ceil_div(MM, 64), 1), 256, CAC<1, 64>::SMEM>>>(
        MM, HID, DD, x2_h, DP, 0, gw1t_h, DP, 0,
        g1, HID, 0, nullptr, 0, 0, nullptr, 0, 0, 0);

    // 11) gsum[b] = sum_n cmean[n]*relu(agg(g1)[b,n]+gb1)
    gcn_gsum<<<BB, HID>>>(g1, gb1, gsum);

    // 12) pool = relu(gsum @ gw2 + gb2)
    sgemm_nt<<<dim3(1, ceil_div(BB, 128), 1), 256>>>(
        BB, HID, HID, gsum, HID, gw2, HID, pool, HID, gb2, 1);

    // 13) out = pool @ lin_w + lin_b (fp32)
    sgemm_nt<<<dim3(1, ceil_div(BB, 128), 1), 256>>>(
        BB, CC, HID, pool, HID, lw, CC, out, CC, lb, 0);
}

// round 15
// speedup vs baseline: 1.2242x; 1.0246x over previous
#include <cuda_runtime.h>
#include <cuda_fp16.h>
#include <cstdint>
#include <math.h>

// ---------------- problem constants ----------------
#define BB   1024
#define IMG  512
#define TXT  300
#define NN   14
#define FF   2048
#define HID  128
#define CC   14
#define EE   182
#define DD   812     // IMG + TXT
#define D3   2436    // 3*D
#define MM   (BB*NN) // 14336 rows
#define DP   816     // DD padded to mult of 8
#define QLD  2448    // 3*DP, qkv fp16 row stride

// ---------------- fp32 scratch ----------------
__device__ float g_qkvi[(size_t)BB * D3];
__device__ float g_qkvt[(size_t)NN * D3];
__device__ float g_S0  [(size_t)BB * BB];
__device__ float g_Bq  [(size_t)NN * BB];
__device__ float g_ovt [(size_t)NN * DD];
__device__ float g_ao2 [(size_t)MM * DD];
__device__ float g_x1  [(size_t)MM * DD];
__device__ float g_ff  [(size_t)MM * DD];
__device__ float g_g1  [(size_t)MM * HID];
__device__ float g_gsum[(size_t)BB * HID];
__device__ float g_pool[(size_t)BB * HID];

// ---------------- fp16 scratch (tensor-core operands) ----------------
__device__ __align__(256) __half g_imgr_h [(size_t)BB * IMG];
__device__ __align__(256) __half g_inwr_h [(size_t)D3 * IMG];
__device__ __align__(256) __half g_outwr_h[(size_t)DD * DP];
__device__ __align__(256) __half g_qkvi_h [(size_t)BB * QLD];
__device__ __align__(256) __half g_VoT_h  [(size_t)DD * BB];
__device__ __align__(256) __half g_attn_h [(size_t)NN * BB * BB];
__device__ __align__(256) __half g_x1r_h  [(size_t)MM * DP];
__device__ __align__(256) __half g_w1t_h  [(size_t)FF * DP];
__device__ __align__(256) __half g_hid_h  [(size_t)MM * FF];
__device__ __align__(256) __half g_w2t_h  [(size_t)DD * FF];
__device__ __align__(256) __half g_x2_h   [(size_t)MM * DP];
__device__ __align__(256) __half g_gw1t_h [(size_t)HID * DP];

__device__ int   g_eoff[NN + 1];
__device__ int   g_esrc[EE + NN + 16];
__device__ float g_ewt [EE + NN + 16];
__device__ float g_cmean[NN];

// ========== fp16 mma.sync GEMM (cp.async 3-stage, BT, ldmatrix frags) =======
// C[m,n] = sum_k A[m,k]*B[n,k] (+bias, relu).  A/B fp16, K-major, 16B-aligned.
// CTA tile (IM*64)x128, 256 threads, 8 warps (4x2), warp tile (IM*16)x64.
// smem rows: RS u32 (KH/2 data + 4 pad) -> LDSM phase-addresses conflict-free.
#define CA_STAGES 3
template <int IM, int KH> struct CAC {
    static const int RS = KH / 2 + 4;
    static const int A_U32 = IM * 64 * RS;
    static const int STAGE_U32 = A_U32 + 128 * RS;
    static const int SMEM = CA_STAGES * STAGE_U32 * 4;
};

template <int IM, int KH>
__device__ __forceinline__ void hfetch(
    int k0, int M, int N, int K,
    const __half* __restrict__ A, long long lda,
    const __half* __restrict__ B, long long ldb,
    int m0, int n0, int tid, uint32_t sA, uint32_t sB) {
    const int RS = CAC<IM, KH>::RS;
    const int CPR = KH / 8;                 // 16B chunks per row
    {
        const int TOT = IM * 64 * CPR;
#pragma unroll
        for (int c = 0; c < TOT / 256; c++) {
            int idx = c * 256 + tid;
            int row = idx / CPR, ch = idx - row * CPR;
            int gm = m0 + row;
            bool mv = gm < M;
            const __half* rp = A + (long long)(mv ? gm : m0) * lda;
            int kh = k0 + ch * 8;
            int rem = K - kh;
            int vb = mv ? (rem >= 8 ? 16 : (rem > 0 ? rem * 2 : 0)) : 0;
            const __half* src = rp + (kh < K ? kh : 0);
            uint32_t dst = sA + (uint32_t)(row * RS + ch * 4) * 4u;
            asm volatile("cp.async.cg.shared.global [%0], [%1], 16, %2;"
                         :: "r"(dst), "l"(src), "r"(vb));
        }
    }
    {
        const int TOT = 128 * CPR;
#pragma unroll
        for (int c = 0; c < TOT / 256; c++) {
            int idx = c * 256 + tid;
            int row = idx / CPR, ch = idx - row * CPR;
            int gj = n0 + row;
            bool nv = gj < N;
            const __half* rp = B + (long long)(nv ? gj : n0) * ldb;
            int kh = k0 + ch * 8;
            int rem = K - kh;
            int vb = nv ? (rem >= 8 ? 16 : (rem > 0 ? rem * 2 : 0)) : 0;
            const __half* src = rp + (kh < K ? kh : 0);
            uint32_t dst = sB + (uint32_t)(row * RS + ch * 4) * 4u;
            asm volatile("cp.async.cg.shared.global [%0], [%1], 16, %2;"
                         :: "r"(dst), "l"(src), "r"(vb));
        }
    }
}

template <int IM, int KH>
__device__ __forceinline__ void hg_core(
    int M, int N, int K,
    const __half* __restrict__ A, long long lda,
    const __half* __restrict__ B, long long ldb,
    float* __restrict__ C, long long ldc,
    __half* __restrict__ Ch, long long ldh,
    const float* __restrict__ bias,
    int relu, int qkvpad,
    int m0, int n0, uint32_t* dsm) {
    if (m0 >= M) return;
    const int RS = CAC<IM, KH>::RS;
    int tid = threadIdx.x;
    int warp = tid >> 5, lane = tid & 31;
    int wm = warp >> 1, wn = warp & 1;
    int gid = lane >> 2, tig = lane & 3;

    uint32_t smem_base = (uint32_t)__cvta_generic_to_shared(dsm);

    // ldmatrix per-lane address selectors (derived from scalar mapping)
    int a_row = (lane & 7) + ((lane >> 3) & 1) * 8;
    int a_col = (lane >> 4) * 4;
    int b_row = (lane & 7) + ((lane >> 4) & 1) * 8;
    int b_col = ((lane >> 3) & 1) * 4;

    uint32_t aoff[IM];
#pragma unroll
    for (int i = 0; i < IM; i++)
        aoff[i] = (uint32_t)(((wm * (IM * 16) + i * 16 + a_row) * RS + a_col) * 4);
    uint32_t boff[4];
#pragma unroll
    for (int jp = 0; jp < 4; jp++)
        boff[jp] = (uint32_t)(((wn * 64 + jp * 16 + b_row) * RS + b_col) * 4)
                   + (uint32_t)(CAC<IM, KH>::A_U32 * 4);

    float c[IM][8][4];
#pragma unroll
    for (int i = 0; i < IM; i++)
#pragma unroll
        for (int j = 0; j < 8; j++)
#pragma unroll
            for (int r = 0; r < 4; r++) c[i][j][r] = 0.f;

    int ntiles = (K + KH - 1) / KH;

#pragma unroll
    for (int t = 0; t < CA_STAGES - 1; t++) {
        if (t < ntiles) {
            uint32_t sa = smem_base + (uint32_t)(t * CAC<IM, KH>::STAGE_U32) * 4u;
            hfetch<IM, KH>(t * KH, M, N, K, A, lda, B, ldb, m0, n0, tid,
                           sa, sa + (uint32_t)CAC<IM, KH>::A_U32 * 4u);
        }
        asm volatile("cp.async.commit_group;");
    }

    for (int t = 0; t < ntiles; t++) {
        asm volatile("cp.async.wait_group %0;" :: "n"(CA_STAGES - 2));
        __syncthreads();

        int nf = t + CA_STAGES - 1;
        if (nf < ntiles) {
            uint32_t sa = smem_base +
                (uint32_t)((nf % CA_STAGES) * CAC<IM, KH>::STAGE_U32) * 4u;
            hfetch<IM, KH>(nf * KH, M, N, K, A, lda, B, ldb, m0, n0, tid,
                           sa, sa + (uint32_t)CAC<IM, KH>::A_U32 * 4u);
        }
        asm volatile("cp.async.commit_group;");

        uint32_t sbase = smem_base +
            (uint32_t)((t % CA_STAGES) * CAC<IM, KH>::STAGE_U32) * 4u;

#pragma unroll
        for (int ks = 0; ks < KH / 16; ks++) {
            uint32_t koff = (uint32_t)(ks * 32);   // 8 u32 per 16-half step
            uint32_t a[IM][4], b[8][2];
#pragma unroll
            for (int i = 0; i < IM; i++) {
                asm volatile(
                    "ldmatrix.sync.aligned.m8n8.x4.shared.b16 {%0,%1,%2,%3}, [%4];"
                    : "=r"(a[i][0]), "=r"(a[i][1]), "=r"(a[i][2]), "=r"(a[i][3])
                    : "r"(sbase + aoff[i] + koff));
            }
#pragma unroll
            for (int jp = 0; jp < 4; jp++) {
                asm volatile(
                    "ldmatrix.sync.aligned.m8n8.x4.shared.b16 {%0,%1,%2,%3}, [%4];"
                    : "=r"(b[2 * jp][0]), "=r"(b[2 * jp][1]),
                      "=r"(b[2 * jp + 1][0]), "=r"(b[2 * jp + 1][1])
                    : "r"(sbase + boff[jp] + koff));
            }
#pragma unroll
            for (int i = 0; i < IM; i++)
#pragma unroll
                for (int j = 0; j < 8; j++) {
                    asm volatile(
                        "mma.sync.aligned.m16n8k16.row.col.f32.f16.f16.f32 "
                        "{%0,%1,%2,%3}, {%4,%5,%6,%7}, {%8,%9}, {%0,%1,%2,%3};"
                        : "+f"(c[i][j][0]), "+f"(c[i][j][1]),
                          "+f"(c[i][j][2]), "+f"(c[i][j][3])
                        : "r"(a[i][0]), "r"(a[i][1]), "r"(a[i][2]), "r"(a[i][3]),
                          "r"(b[j][0]), "r"(b[j][1]));
                }
        }
    }

    // ---- epilogue ----
#pragma unroll
    for (int i = 0; i < IM; i++) {
        int r0 = m0 + wm * (IM * 16) + i * 16 + gid;
#pragma unroll
        for (int j = 0; j < 8; j++) {
            int c0 = n0 + wn * 64 + j * 8 + 2 * tig;
#pragma unroll
            for (int rr = 0; rr < 2; rr++) {
                int gm = r0 + rr * 8;
                if (gm >= M) continue;
#pragma unroll
                for (int cc = 0; cc < 2; cc++) {
                    int gn = c0 + cc;
                    if (gn >= N) continue;
                    float v = c[i][j][rr * 2 + cc];
                    if (bias) v += bias[gn];
                    if (relu) v = fmaxf(v, 0.f);
                    if (C) C[(long long)gm * ldc + gn] = v;
                    if (Ch) {
                        int col = gn;
                        if (qkvpad) {
                            int seg = (gn >= 2 * DD) ? 2 : (gn >= DD ? 1 : 0);
                            col = seg * DP + (gn - seg * DD);
                        }
                        Ch[(long long)gm * ldh + col] = __float2half_rn(v);
                    }
                }
            }
        }
    }
}

template <int IM, int KH>
__global__ __launch_bounds__(256, 2)
void hgemm(int M, int N, int K,
           const __half* __restrict__ A, long long lda, long long sA,
           const __half* __restrict__ B, long long ldb, long long sB,
           float* __restrict__ C, long long ldc, long long sC,
           __half* __restrict__ Ch, long long ldh, long long sCh,
           const float* __restrict__ bias, long long sBias,
           int relu, int qkvpad) {
    extern __shared__ uint32_t dsm[];
    int z = blockIdx.z;
    A += (long long)z * sA;
    B += (long long)z * sB;
    if (C) C += (long long)z * sC;
    if (Ch) Ch += (long long)z * sCh;
    if (bias) bias += (long long)z * sBias;
    hg_core<IM, KH>(M, N, K, A, lda, B, ldb, C, ldc, Ch, ldh, bias,
                    relu, qkvpad, blockIdx.y * (IM * 64), blockIdx.x * 128, dsm);
}

// ---- dual fp16 GEMM (S0 || VoT), IM=1/KH=64, z selects ----
struct HG {
    const __half* A; const __half* B; float* C; __half* Ch;
    long long lda, ldb, ldc, ldh;
    int M, N, K;
};

__global__ __launch_bounds__(256, 2)
void hg_dual(HG a0, HG a1) {
    extern __shared__ uint32_t dsm[];
    const HG& g = (blockIdx.z == 0) ? a0 : a1;
    hg_core<1, 64>(g.M, g.N, g.K, g.A, g.lda, g.B, g.ldb, g.C, g.ldc,
                   g.Ch, g.ldh, nullptr, 0, 0,
                   blockIdx.y * 64, blockIdx.x * 128, dsm);
}

// ================= thin GEMM body (M == 14, fp32) =================
__device__ __forceinline__ void thin_body(
    int bid, int N, int K,
    const float* __restrict__ A, long long lda,
    const float* __restrict__ B, long long ldb,
    float* __restrict__ C, long long ldc,
    const float* __restrict__ bias, float* sAm) {
    int tid = threadIdx.x;
    int K4 = K >> 2;
    for (int idx = tid; idx < NN * K4; idx += 256) {
        int m = idx / K4, k4 = idx - m * K4;
        *(float4*)&sAm[m * 816 + k4 * 4] =
            *(const float4*)(A + (long long)m * lda + k4 * 4);
    }
    __syncthreads();

    int n = bid * 8 + (tid >> 5);
    int lane = tid & 31;
    float acc[NN];
#pragma unroll
    for (int m = 0; m < NN; m++) acc[m] = 0.f;

    if (n < N) {
        const float* Bp = B + (long long)n * ldb;
        for (int k = lane * 4; k + 4 <= K; k += 128) {
            float4 bv = *(const float4*)(Bp + k);
#pragma unroll
            for (int m = 0; m < NN; m++) {
                float4 av = *(const float4*)&sAm[m * 816 + k];
                acc[m] += av.x * bv.x + av.y * bv.y + av.z * bv.z + av.w * bv.w;
            }
        }
    }
#pragma unroll
    for (int off = 16; off; off >>= 1)
#pragma unroll
        for (int m = 0; m < NN; m++)
            acc[m] += __shfl_down_sync(0xffffffffu, acc[m], off);

    if (lane == 0 && n < N) {
        float bz = bias ? bias[n] : 0.f;
#pragma unroll
        for (int m = 0; m < NN; m++)
            C[(long long)m * ldc + n] = acc[m] + bz;
    }
}

// ---- prep: fp16 converts (3 segs) + qkvt thin + edge_prep(+cmean) ----
struct CSeg { const float* src; __half* dst; int scols, ccols, dld; long long total; };
struct PrepArgs {
    CSeg s[3];
    int nb[3];
    const float* we; const float* inw; const float* inb; float* qkvt;
    const int* ei;
};

__global__ __launch_bounds__(256)
void prep_kernel(PrepArgs pa) {
    __shared__ float sAm[NN * 816];
    int bid = blockIdx.x;
#pragma unroll
    for (int k = 0; k < 3; k++) {
        if (bid < pa.nb[k]) {
            const CSeg& s = pa.s[k];
            long long base = (long long)bid * 1024 + threadIdx.x * 4;
#pragma unroll
            for (int e = 0; e < 4; e++) {
                long long i = base + e;
                if (i < s.total) {
                    int r = (int)(i / s.ccols), c = (int)(i % s.ccols);
                    s.dst[(long long)r * s.dld + c] =
                        __float2half_rn(s.src[(long long)r * s.scols + c]);
                }
            }
            return;
        }
        bid -= pa.nb[k];
    }
    const int NB_QKVT = (D3 + 7) / 8;
    if (bid < NB_QKVT) {
        thin_body(bid, D3, TXT, pa.we, TXT, pa.inw + IMG, DD,
                  pa.qkvt, D3, pa.inb, sAm);
        return;
    }
    if (threadIdx.x != 0) return;
    const int* ei = pa.ei;
    float deg[NN]; int cnt[NN];
    for (int n = 0; n < NN; n++) { deg[n] = 0.f; cnt[n] = 0; }
    for (int e = 0; e < EE; e++) { int d = ei[EE + e]; deg[d] += 1.f; cnt[d]++; }
    for (int n = 0; n < NN; n++) { deg[n] += 1.f; cnt[n]++; }
    float dinv[NN];
    for (int n = 0; n < NN; n++) dinv[n] = (deg[n] > 0.f) ? rsqrtf(deg[n]) : 0.f;
    int off = 0, pos[NN];
    for (int n = 0; n < NN; n++) { g_eoff[n] = off; pos[n] = off; off += cnt[n]; }
    g_eoff[NN] = off;
    for (int e = 0; e < EE; e++) {
        int d = ei[EE + e], s = ei[e];
        int p = pos[d]++;
        g_esrc[p] = s;
        g_ewt[p]  = dinv[s] * dinv[d];
    }
    for (int n = 0; n < NN; n++) {
        int p = pos[n]++;
        g_esrc[p] = n;
        g_ewt[p]  = dinv[n] * dinv[n];
    }
    float cm[NN];
    for (int n = 0; n < NN; n++) cm[n] = 0.f;
    for (int e = 0; e < EE + NN; e++) cm[g_esrc[e]] += g_ewt[e];
    for (int n = 0; n < NN; n++) g_cmean[n] = cm[n] / (float)NN;
}

// ---- fused transpose+fp16 multi (3 segments) ----
struct TSeg { const float* src; __half* dst; int R, C, dld, nbx, nby; };
struct TTab { TSeg s[3]; int nb[3]; };

__global__ void transpose_multi(TTab tt) {
    __shared__ float t[32][33];
    int bid = blockIdx.x;
    int seg = 0;
#pragma unroll
    for (int k = 0; k < 3; k++) {
        if (bid < tt.nb[k]) { seg = k; break; }
        bid -= tt.nb[k];
    }
    const TSeg& s = tt.s[seg];
    int bx = bid % s.nbx, by = bid / s.nbx;
    int c0 = bx * 32, r0 = by * 32;
    int x = threadIdx.x, y = threadIdx.y;
#pragma unroll
    for (int j = 0; j < 4; j++) {
        int r = r0 + y + j * 8;
        if (r < s.R && c0 + x < s.C)
            t[y + j * 8][x] = s.src[(long long)r * s.C + c0 + x];
    }
    __syncthreads();
#pragma unroll
    for (int j = 0; j < 4; j++) {
        int c = c0 + y + j * 8;
        if (c < s.C && r0 + x < s.R)
            s.dst[(long long)c * s.dld + r0 + x] = __float2half_rn(t[x][y + j * 8]);
    }
}

// ---- fused thin pair: Bq + ovt ----
struct TPairArgs {
    int nb0;
    int N0, K0; const float* A0; long long lda0; const float* B0; long long ldb0;
    float* C0; long long ldc0; const float* bias0;
    int N1, K1; const float* A1; long long lda1; const float* B1; long long ldb1;
    float* C1; long long ldc1; const float* bias1;
};

__global__ __launch_bounds__(256)
void thin_pair(TPairArgs t) {
    __shared__ float sAm[NN * 816];
    int bid = blockIdx.x;
    if (bid < t.nb0)
        thin_body(bid, t.N0, t.K0, t.A0, t.lda0, t.B0, t.ldb0,
                  t.C0, t.ldc0, t.bias0, sAm);
    else
        thin_body(bid - t.nb0, t.N1, t.K1, t.A1, t.lda1, t.B1, t.ldb1,
                  t.C1, t.ldc1, t.bias1, sAm);
}

// ---------------- fp32 tiled SGEMM (small layers) ----------------
__global__ __launch_bounds__(256)
void sgemm_nt(int M, int N, int K,
              const float* __restrict__ A, long long lda,
              const float* __restrict__ B, long long ldb,
              float* __restrict__ C, long long ldc,
              const float* __restrict__ bias, int relu) {
    const int BM = 128, BN = 128, BK = 8;
    __shared__ float As[BK][BM];
    __shared__ float Bs[BK][BN];

    int m0 = blockIdx.y * BM;
    int n0 = blockIdx.x * BN;
    int tid = threadIdx.x;
    int tx = tid & 15, ty = tid >> 4;
    int arow = tid >> 1, acol = (tid & 1) * 4;
    int bnrow = tid >> 5, bncol = (tid & 31) * 4;

    float acc[8][8];
#pragma unroll
    for (int i = 0; i < 8; i++)
#pragma unroll
        for (int j = 0; j < 8; j++) acc[i][j] = 0.f;

    for (int k0 = 0; k0 < K; k0 += BK) {
        {
            int gm = m0 + arow, gk = k0 + acol;
            float4 v = make_float4(0.f, 0.f, 0.f, 0.f);
            if (gm < M && gk < K) {
                const float* p = A + (long long)gm * lda + gk;
                float t[4] = {0.f, 0.f, 0.f, 0.f};
#pragma unroll
                for (int i = 0; i < 4; i++) if (gk + i < K) t[i] = p[i];
                v = make_float4(t[0], t[1], t[2], t[3]);
            }
            As[acol + 0][arow] = v.x; As[acol + 1][arow] = v.y;
            As[acol + 2][arow] = v.z; As[acol + 3][arow] = v.w;
        }
        {
            int gk = k0 + bnrow, gj = n0 + bncol;
            float4 v = make_float4(0.f, 0.f, 0.f, 0.f);
            if (gk < K) {
                const float* p = B + (long long)gk * ldb + gj;
                float t[4] = {0.f, 0.f, 0.f, 0.f};
#pragma unroll
                for (int i = 0; i < 4; i++) if (gj + i < N) t[i] = p[i];
                v = make_float4(t[0], t[1], t[2], t[3]);
            }
            *(float4*)&Bs[bnrow][bncol] = v;
        }
        __syncthreads();

#pragma unroll
        for (int kk = 0; kk < BK; kk++) {
            float a[8], b[8];
#pragma unroll
            for (int i = 0; i < 8; i++) a[i] = As[kk][ty * 8 + i];
#pragma unroll
            for (int j = 0; j < 8; j++) b[j] = Bs[kk][tx * 8 + j];
#pragma unroll
            for (int i = 0; i < 8; i++)
#pragma unroll
                for (int j = 0; j < 8; j++) acc[i][j] = fmaf(a[i], b[j], acc[i][j]);
        }
        __syncthreads();
    }

#pragma unroll
    for (int i = 0; i < 8; i++) {
        int gm = m0 + ty * 8 + i;
        if (gm >= M) continue;
#pragma unroll
        for (int j = 0; j < 8; j++) {
            int gn = n0 + tx * 8 + j;
            if (gn >= N) continue;
            float v = acc[i][j];
            if (bias) v += bias[gn];
            if (relu) v = fmaxf(v, 0.f);
            C[(long long)gm * ldc + gn] = v;
        }
    }
}

// ------- fused softmax (fp16 store) ---
__global__ void softmax_fused(const float* __restrict__ S0,
                              const float* __restrict__ Bq,
                              __half* __restrict__ attn, float scale) {
    int l = blockIdx.x;
    int n = blockIdx.y;
    const float* s0 = S0 + (long long)l * BB;
    const float* bq = Bq + (long long)n * BB;
    __half* out = attn + ((long long)n * BB + l) * BB;

    int t = threadIdx.x;
    float v[4];
#pragma unroll
    for (int i = 0; i < 4; i++) {
        int m = t + i * 256;
        v[i] = scale * (s0[m] + bq[m]);
    }

    float mx = fmaxf(fmaxf(v[0], v[1]), fmaxf(v[2], v[3]));
#pragma unroll
    for (int o = 16; o; o >>= 1) mx = fmaxf(mx, __shfl_xor_sync(0xffffffffu, mx, o));
    __shared__ float sm[8];
    int lane = t & 31, wid = t >> 5;
    if (!lane) sm[wid] = mx;
    __syncthreads();
    if (t == 0) {
        float m = sm[0];
        for (int i = 1; i < 8; i++) m = fmaxf(m, sm[i]);
        sm[0] = m;
    }
    __syncthreads();
    mx = sm[0];

    float s = 0.f;
#pragma unroll
    for (int i = 0; i < 4; i++) { v[i] = __expf(v[i] - mx); s += v[i]; }
#pragma unroll
    for (int o = 16; o; o >>= 1) s += __shfl_xor_sync(0xffffffffu, s, o);
    __syncthreads();
    if (!lane) sm[wid] = s;
    __syncthreads();
    if (t == 0) {
        float a = 0.f;
        for (int i = 0; i < 8; i++) a += sm[i];
        sm[0] = a;
    }
    __syncthreads();
    float inv = 1.f / sm[0];
#pragma unroll
    for (int i = 0; i < 4; i++)
        out[t + i * 256] = __float2half_rn(v[i] * inv);
}

// -------- LN1: x1 = LN(node + ao2); fp32 + fp16 copies -----------
__global__ void ln1_kernel(const float* __restrict__ img, const float* __restrict__ we,
                           const float* __restrict__ R,
                           const float* __restrict__ g, const float* __restrict__ bb,
                           float* __restrict__ out, __half* __restrict__ outh) {
    const int D = DD;
    long long row = blockIdx.x;
    int b = (int)(row / NN);
    int n = (int)(row % NN);
    __shared__ float buf[DD];
    __shared__ float w1s[8], w2s[8];
    const float* ig = img + (long long)b * IMG;
    const float* w  = we + (long long)n * TXT;
    const float* r  = R + row * D;
    float s = 0.f, s2 = 0.f;
    for (int i = threadIdx.x; i < D; i += 256) {
        float nd = (i < IMG) ? ig[i] : w[i - IMG];
        float v = nd + r[i];
        buf[i] = v;
        s += v; s2 += v * v;
    }
#pragma unroll
    for (int o = 16; o; o >>= 1) {
        s  += __shfl_down_sync(0xffffffffu, s, o);
        s2 += __shfl_down_sync(0xffffffffu, s2, o);
    }
    int lane = threadIdx.x & 31, wid = threadIdx.x >> 5;
    if (!lane) { w1s[wid] = s; w2s[wid] = s2; }
    __syncthreads();
    if (threadIdx.x == 0) {
        float a = 0.f, b2 = 0.f;
        for (int i = 0; i < 8; i++) { a += w1s[i]; b2 += w2s[i]; }
        w1s[0] = a; w2s[0] = b2;
    }
    __syncthreads();
    float mean = w1s[0] / D;
    float var  = w2s[0] / D - mean * mean;
    float inv  = rsqrtf(var + 1e-5f);
    float* o = out + row * D;
    __half* oh = outh + row * DP;
    for (int i = threadIdx.x; i < D; i += 256) {
        float v = (buf[i] - mean) * inv * g[i] + bb[i];
        o[i] = v;
        oh[i] = __float2half_rn(v);
    }
}

// ---------------- LN2: x2_h = fp16(LN(X + R)) ----------------
__global__ void ln_kernel(const float* __restrict__ X, const float* __restrict__ R,
                          const float* __restrict__ g, const float* __restrict__ bb,
                          __half* __restrict__ outh) {
    const int D = DD;
    long long row = blockIdx.x;
    __shared__ float buf[DD];
    __shared__ float w1s[8], w2s[8];
    const float* x = X + row * D;
    const float* r = R + row * D;
    float s = 0.f, s2 = 0.f;
    for (int i = threadIdx.x; i < D; i += 256) {
        float v = x[i] + r[i];
        buf[i] = v;
        s += v; s2 += v * v;
    }
#pragma unroll
    for (int o = 16; o; o >>= 1) {
        s  += __shfl_down_sync(0xffffffffu, s, o);
        s2 += __shfl_down_sync(0xffffffffu, s2, o);
    }
    int lane = threadIdx.x & 31, wid = threadIdx.x >> 5;
    if (!lane) { w1s[wid] = s; w2s[wid] = s2; }
    __syncthreads();
    if (threadIdx.x == 0) {
        float a = 0.f, b2 = 0.f;
        for (int i = 0; i < 8; i++) { a += w1s[i]; b2 += w2s[i]; }
        w1s[0] = a; w2s[0] = b2;
    }
    __syncthreads();
    float mean = w1s[0] / D;
    float var  = w2s[0] / D - mean * mean;
    float inv  = rsqrtf(var + 1e-5f);
    __half* oh = outh + row * DP;
    for (int i = threadIdx.x; i < D; i += 256)
        oh[i] = __float2half_rn((buf[i] - mean) * inv * g[i] + bb[i]);
}

// ------ GCN tail: gsum[b][h] = sum_dst cmean[dst]*relu(agg(g1)[b,dst,h]+gb1[h])
__global__ __launch_bounds__(HID)
void gcn_gsum(const float* __restrict__ g1, const float* __restrict__ gb1,
              float* __restrict__ gsum) {
    __shared__ float sg[NN][HID];
    int b = blockIdx.x;
    int h = threadIdx.x;
    const float* base = g1 + (long long)b * NN * HID;
#pragma unroll
    for (int n = 0; n < NN; n++) sg[n][h] = base[n * HID + h];
    float bz = gb1[h];
    float acc = 0.f;
#pragma unroll
    for (int dst = 0; dst < NN; dst++) {
        float a = bz;
        int e0 = g_eoff[dst], e1 = g_eoff[dst + 1];
        for (int e = e0; e < e1; e++)
            a += g_ewt[e] * sg[g_esrc[e]][h];
        a = fmaxf(a, 0.f);
        acc += g_cmean[dst] * a;
    }
    gsum[(long long)b * HID + h] = acc;
}

// ---------------- launch ----------------
static inline int ceil_div(int a, int b) { return (a + b - 1) / b; }

extern "C" void kernel_launch(void* const* d_in, const int* in_sizes, int n_in,
                              void* d_out, int out_size) {
    const float* img   = (const float*)d_in[0];
    const float* we    = (const float*)d_in[1];
    const int*   ei    = (const int*)  d_in[2];
    const float* inw   = (const float*)d_in[3];
    const float* inb   = (const float*)d_in[4];
    const float* outw  = (const float*)d_in[5];
    const float* outb  = (const float*)d_in[6];
    const float* ln1g  = (const float*)d_in[7];
    const float* ln1b  = (const float*)d_in[8];
    const float* ln2g  = (const float*)d_in[9];
    const float* ln2b  = (const float*)d_in[10];
    const float* w1    = (const float*)d_in[11];
    const float* b1    = (const float*)d_in[12];
    const float* w2    = (const float*)d_in[13];
    const float* b2    = (const float*)d_in[14];
    const float* gw1   = (const float*)d_in[15];
    const float* gb1   = (const float*)d_in[16];
    const float* gw2   = (const float*)d_in[17];
    const float* gb2   = (const float*)d_in[18];
    const float* lw    = (const float*)d_in[19];
    const float* lb    = (const float*)d_in[20];
    float* out = (float*)d_out;

    float *qkvi, *qkvt, *S0, *Bq, *ovt, *ao2, *x1, *ff, *g1, *gsum, *pool;
    __half *imgr_h, *inwr_h, *outwr_h, *qkvi_h, *VoT_h, *attn_h, *x1r_h;
    __half *w1t_h, *hid_h, *w2t_h, *x2_h, *gw1t_h;
    cudaGetSymbolAddress((void**)&qkvi, g_qkvi);
    cudaGetSymbolAddress((void**)&qkvt, g_qkvt);
    cudaGetSymbolAddress((void**)&S0,   g_S0);
    cudaGetSymbolAddress((void**)&Bq,   g_Bq);
    cudaGetSymbolAddress((void**)&ovt,  g_ovt);
    cudaGetSymbolAddress((void**)&ao2,  g_ao2);
    cudaGetSymbolAddress((void**)&x1,   g_x1);
    cudaGetSymbolAddress((void**)&ff,   g_ff);
    cudaGetSymbolAddress((void**)&g1,   g_g1);
    cudaGetSymbolAddress((void**)&gsum, g_gsum);
    cudaGetSymbolAddress((void**)&pool, g_pool);
    cudaGetSymbolAddress((void**)&imgr_h,  g_imgr_h);
    cudaGetSymbolAddress((void**)&inwr_h,  g_inwr_h);
    cudaGetSymbolAddress((void**)&outwr_h, g_outwr_h);
    cudaGetSymbolAddress((void**)&qkvi_h,  g_qkvi_h);
    cudaGetSymbolAddress((void**)&VoT_h,   g_VoT_h);
    cudaGetSymbolAddress((void**)&attn_h,  g_attn_h);
    cudaGetSymbolAddress((void**)&x1r_h,   g_x1r_h);
    cudaGetSymbolAddress((void**)&w1t_h,   g_w1t_h);
    cudaGetSymbolAddress((void**)&hid_h,   g_hid_h);
    cudaGetSymbolAddress((void**)&w2t_h,   g_w2t_h);
    cudaGetSymbolAddress((void**)&x2_h,    g_x2_h);
    cudaGetSymbolAddress((void**)&gw1t_h,  g_gw1t_h);

    cudaFuncSetAttribute(hgemm<2, 64>,
                         cudaFuncAttributeMaxDynamicSharedMemorySize, CAC<2, 64>::SMEM);
    cudaFuncSetAttribute(hgemm<1, 64>,
                         cudaFuncAttributeMaxDynamicSharedMemorySize, CAC<1, 64>::SMEM);
    cudaFuncSetAttribute(hg_dual,
                         cudaFuncAttributeMaxDynamicSharedMemorySize, CAC<1, 64>::SMEM);

    const float attn_scale = 1.0f / sqrtf((float)DD);

    // 0) PREP: fp16 converts + qkvt thin + edge_prep(+cmean)
    {
        PrepArgs pa;
        pa.s[0] = { img,  imgr_h,  IMG, IMG, IMG, (long long)BB * IMG };
        pa.s[1] = { inw,  inwr_h,  DD,  IMG, IMG, (long long)D3 * IMG };
        pa.s[2] = { outw, outwr_h, DD,  DD,  DP,  (long long)DD * DD };
        int nblocks = 0;
        for (int k = 0; k < 3; k++) {
            pa.nb[k] = (int)((pa.s[k].total + 1023) / 1024);
            nblocks += pa.nb[k];
        }
        pa.we = we; pa.inw = inw; pa.inb = inb; pa.qkvt = qkvt; pa.ei = ei;
        nblocks += ceil_div(D3, 8) + 1;
        prep_kernel<<<nblocks, 256>>>(pa);
    }
    // 0b) transposed fp16 weights (one launch: w1, w2, gw1)
    {
        TTab tt;
        tt.s[0] = { w1,  w1t_h,  DD, FF,  DP, ceil_div(FF, 32),  ceil_div(DD, 32) };
        tt.s[1] = { w2,  w2t_h,  FF, DD,  FF, ceil_div(DD, 32),  ceil_div(FF, 32) };
        tt.s[2] = { gw1, gw1t_h, DD, HID, DP, ceil_div(HID, 32), ceil_div(DD, 32) };
        int nb = 0;
        for (int k = 0; k < 3; k++) {
            tt.nb[k] = tt.s[k].nbx * tt.s[k].nby;
            nb += tt.nb[k];
        }
        transpose_multi<<<nb, dim3(32, 8)>>>(tt);
    }

    // 1) qkvi = img @ Win[:, :512]^T  -> fp32 qkvi + padded fp16 qkvi_h
    hgemm<2, 64><<<dim3(ceil_div(D3, 128), 8, 1), 256, CAC<2, 64>::SMEM>>>(
        BB, D3, IMG, imgr_h, IMG, 0, inwr_h, IMG, 0,
        qkvi, D3, 0, qkvi_h, QLD, 0, nullptr, 0, 0, 1);

    // 2) DUAL: S0 = qi@ki^T (fp32) || VoT = Wout@vi^T (fp16)
    {
        HG a0, a1;
        a0.A = qkvi_h; a0.lda = QLD; a0.B = qkvi_h + DP; a0.ldb = QLD;
        a0.C = S0; a0.ldc = BB; a0.Ch = nullptr; a0.ldh = 0;
        a0.M = BB; a0.N = BB; a0.K = DD;
        a1.A = outwr_h; a1.lda = DP; a1.B = qkvi_h + 2 * DP; a1.ldb = QLD;
        a1.C = nullptr; a1.ldc = 0; a1.Ch = VoT_h; a1.ldh = BB;
        a1.M = DD; a1.N = BB; a1.K = DD;
        hg_dual<<<dim3(8, 16, 2), 256, CAC<1, 64>::SMEM>>>(a0, a1);
    }

    // 3) DUAL thin: Bq || ovt (fp32)
    {
        TPairArgs tp;
        tp.nb0 = ceil_div(BB, 8);
        tp.N0 = BB; tp.K0 = DD; tp.A0 = qkvt; tp.lda0 = D3;
        tp.B0 = qkvi + DD; tp.ldb0 = D3; tp.C0 = Bq; tp.ldc0 = BB; tp.bias0 = nullptr;
        tp.N1 = DD; tp.K1 = DD; tp.A1 = qkvt + 2 * DD; tp.lda1 = D3;
        tp.B1 = outw; tp.ldb1 = DD; tp.C1 = ovt; tp.ldc1 = DD; tp.bias1 = outb;
        thin_pair<<<tp.nb0 + ceil_div(DD, 8), 256>>>(tp);
    }

    // 4) attn_h = fp16(softmax(scale*(S0 + Bq)))
    softmax_fused<<<dim3(BB, NN), 256>>>(S0, Bq, attn_h, attn_scale);

    // 5) ao2[l,n,:] = attn_n @ VoT^T + ovt[n]  (fp32 out, batched over n)
    hgemm<2, 64><<<dim3(ceil_div(DD, 128), 8, NN), 256, CAC<2, 64>::SMEM>>>(
        BB, DD, BB,
        attn_h, BB, (long long)BB * BB,
        VoT_h, BB, 0,
        ao2, (long long)NN * DD, DD,
        nullptr, 0, 0,
        ovt, DD, 0, 0);

    // 6) x1 = LN(node + ao2); x1r_h fp16
    ln1_kernel<<<MM, 256>>>(img, we, ao2, ln1g, ln1b, x1, x1r_h);

    // 7) hid_h = fp16(relu(x1r @ w1^T + b1))
    hgemm<2, 64><<<dim3(ceil_div(FF, 128), ceil_div(MM, 128), 1), 256, CAC<2, 64>::SMEM>>>(
        MM, FF, DD, x1r_h, DP, 0, w1t_h, DP, 0,
        nullptr, 0, 0, hid_h, FF, 0, b1, 0, 1, 0);

    // 8) ff = hid @ w2^T + b2 (fp32)
    hgemm<2, 64><<<dim3(ceil_div(DD, 128), ceil_div(MM, 128), 1), 256, CAC<2, 64>::SMEM>>>(
        MM, DD, FF, hid_h, FF, 0, w2t_h, FF, 0,
        ff, DD, 0, nullptr, 0, 0, b2, 0, 0, 0);

    // 9) x2_h = fp16(LN(x1 + ff))
    ln_kernel<<<MM, 256>>>(x1, ff, ln2g, ln2b, x2_h);

    // 10) g1 = x2 @ gw1^T (fp32)
    hgemm<1, 64><<<dim3(1, ceil_div(MM, 64), 1), 256, CAC<1, 64>::SMEM>>>(
        MM, HID, DD, x2_h, DP, 0, gw1t_h, DP, 0,
        g1, HID, 0, nullptr, 0, 0, nullptr, 0, 0, 0);

    // 11) gsum[b] = sum_n cmean[n]*relu(agg(g1)[b,n]+gb1)
    gcn_gsum<<<BB, HID>>>(g1, gb1, gsum);

    // 12) pool = relu(gsum @ gw2 + gb2)
    sgemm_nt<<<dim3(1, ceil_div(BB, 128), 1), 256>>>(
        BB, HID, HID, gsum, HID, gw2, HID, pool, HID, gb2, 1);

    // 13) out = pool @ lin_w + lin_b (fp32)
    sgemm_nt<<<dim3(1, ceil_div(BB, 128), 1), 256>>>(
        BB, CC, HID, pool, HID, lw, CC, out, CC, lb, 0);
}

// round 16
// speedup vs baseline: 1.2826x; 1.0477x over previous
#include <cuda_runtime.h>
#include <cuda_fp16.h>
#include <cstdint>
#include <math.h>

// ---------------- problem constants ----------------
#define BB   1024
#define IMG  512
#define TXT  300
#define NN   14
#define FF   2048
#define HID  128
#define CC   14
#define EE   182
#define DD   812     // IMG + TXT
#define D3   2436    // 3*D
#define MM   (BB*NN) // 14336 rows
#define DP   816     // DD padded to mult of 8
#define QLD  2448    // 3*DP, qkv fp16 row stride

// ---------------- fp32 scratch ----------------
__device__ float g_qkvi[(size_t)BB * D3];
__device__ float g_qkvt[(size_t)NN * D3];
__device__ float g_S0  [(size_t)BB * BB];
__device__ float g_Bq  [(size_t)NN * BB];
__device__ float g_ovt [(size_t)NN * DD];
__device__ float g_x1  [(size_t)MM * DD];
__device__ float g_ff  [(size_t)MM * DD];
__device__ float g_g1  [(size_t)MM * HID];
__device__ float g_gsum[(size_t)BB * HID];

// ---------------- fp16 scratch (tensor-core operands) ----------------
__device__ __align__(256) __half g_imgr_h [(size_t)BB * IMG];
__device__ __align__(256) __half g_inwr_h [(size_t)D3 * IMG];
__device__ __align__(256) __half g_outwr_h[(size_t)DD * DP];
__device__ __align__(256) __half g_qkvi_h [(size_t)BB * QLD];
__device__ __align__(256) __half g_VoT_h  [(size_t)DD * BB];
__device__ __align__(256) __half g_attn_h [(size_t)NN * BB * BB];
__device__ __align__(256) __half g_ao2_h  [(size_t)MM * DD];
__device__ __align__(256) __half g_x1r_h  [(size_t)MM * DP];
__device__ __align__(256) __half g_w1t_h  [(size_t)FF * DP];
__device__ __align__(256) __half g_hid_h  [(size_t)MM * FF];
__device__ __align__(256) __half g_w2t_h  [(size_t)DD * FF];
__device__ __align__(256) __half g_x2_h   [(size_t)MM * DP];
__device__ __align__(256) __half g_gw1t_h [(size_t)HID * DP];

__device__ int   g_eoff[NN + 1];
__device__ int   g_esrc[EE + NN + 16];
__device__ float g_ewt [EE + NN + 16];
__device__ float g_cmean[NN];

// ========== fp16 mma.sync GEMM (cp.async 3-stage, BT, ldmatrix frags) =======
#define CA_STAGES 3
template <int IM, int KH> struct CAC {
    static const int RS = KH / 2 + 4;
    static const int A_U32 = IM * 64 * RS;
    static const int STAGE_U32 = A_U32 + 128 * RS;
    static const int SMEM = CA_STAGES * STAGE_U32 * 4;
};

template <int IM, int KH>
__device__ __forceinline__ void hfetch(
    int k0, int M, int N, int K,
    const __half* __restrict__ A, long long lda,
    const __half* __restrict__ B, long long ldb,
    int m0, int n0, int tid, uint32_t sA, uint32_t sB) {
    const int RS = CAC<IM, KH>::RS;
    const int CPR = KH / 8;
    {
        const int TOT = IM * 64 * CPR;
#pragma unroll
        for (int c = 0; c < TOT / 256; c++) {
            int idx = c * 256 + tid;
            int row = idx / CPR, ch = idx - row * CPR;
            int gm = m0 + row;
            bool mv = gm < M;
            const __half* rp = A + (long long)(mv ? gm : m0) * lda;
            int kh = k0 + ch * 8;
            int rem = K - kh;
            int vb = mv ? (rem >= 8 ? 16 : (rem > 0 ? rem * 2 : 0)) : 0;
            const __half* src = rp + (kh < K ? kh : 0);
            uint32_t dst = sA + (uint32_t)(row * RS + ch * 4) * 4u;
            asm volatile("cp.async.cg.shared.global [%0], [%1], 16, %2;"
                         :: "r"(dst), "l"(src), "r"(vb));
        }
    }
    {
        const int TOT = 128 * CPR;
#pragma unroll
        for (int c = 0; c < TOT / 256; c++) {
            int idx = c * 256 + tid;
            int row = idx / CPR, ch = idx - row * CPR;
            int gj = n0 + row;
            bool nv = gj < N;
            const __half* rp = B + (long long)(nv ? gj : n0) * ldb;
            int kh = k0 + ch * 8;
            int rem = K - kh;
            int vb = nv ? (rem >= 8 ? 16 : (rem > 0 ? rem * 2 : 0)) : 0;
            const __half* src = rp + (kh < K ? kh : 0);
            uint32_t dst = sB + (uint32_t)(row * RS + ch * 4) * 4u;
            asm volatile("cp.async.cg.shared.global [%0], [%1], 16, %2;"
                         :: "r"(dst), "l"(src), "r"(vb));
        }
    }
}

template <int IM, int KH>
__device__ __forceinline__ void hg_core(
    int M, int N, int K,
    const __half* __restrict__ A, long long lda,
    const __half* __restrict__ B, long long ldb,
    float* __restrict__ C, long long ldc,
    __half* __restrict__ Ch, long long ldh,
    const float* __restrict__ bias,
    int relu, int qkvpad,
    int m0, int n0, uint32_t* dsm) {
    if (m0 >= M) return;
    const int RS = CAC<IM, KH>::RS;
    int tid = threadIdx.x;
    int warp = tid >> 5, lane = tid & 31;
    int wm = warp >> 1, wn = warp & 1;
    int gid = lane >> 2, tig = lane & 3;

    uint32_t smem_base = (uint32_t)__cvta_generic_to_shared(dsm);

    int a_row = (lane & 7) + ((lane >> 3) & 1) * 8;
    int a_col = (lane >> 4) * 4;
    int b_row = (lane & 7) + ((lane >> 4) & 1) * 8;
    int b_col = ((lane >> 3) & 1) * 4;

    uint32_t aoff[IM];
#pragma unroll
    for (int i = 0; i < IM; i++)
        aoff[i] = (uint32_t)(((wm * (IM * 16) + i * 16 + a_row) * RS + a_col) * 4);
    uint32_t boff[4];
#pragma unroll
    for (int jp = 0; jp < 4; jp++)
        boff[jp] = (uint32_t)(((wn * 64 + jp * 16 + b_row) * RS + b_col) * 4)
                   + (uint32_t)(CAC<IM, KH>::A_U32 * 4);

    float c[IM][8][4];
#pragma unroll
    for (int i = 0; i < IM; i++)
#pragma unroll
        for (int j = 0; j < 8; j++)
#pragma unroll
            for (int r = 0; r < 4; r++) c[i][j][r] = 0.f;

    int ntiles = (K + KH - 1) / KH;

#pragma unroll
    for (int t = 0; t < CA_STAGES - 1; t++) {
        if (t < ntiles) {
            uint32_t sa = smem_base + (uint32_t)(t * CAC<IM, KH>::STAGE_U32) * 4u;
            hfetch<IM, KH>(t * KH, M, N, K, A, lda, B, ldb, m0, n0, tid,
                           sa, sa + (uint32_t)CAC<IM, KH>::A_U32 * 4u);
        }
        asm volatile("cp.async.commit_group;");
    }

    for (int t = 0; t < ntiles; t++) {
        asm volatile("cp.async.wait_group %0;" :: "n"(CA_STAGES - 2));
        __syncthreads();

        int nf = t + CA_STAGES - 1;
        if (nf < ntiles) {
            uint32_t sa = smem_base +
                (uint32_t)((nf % CA_STAGES) * CAC<IM, KH>::STAGE_U32) * 4u;
            hfetch<IM, KH>(nf * KH, M, N, K, A, lda, B, ldb, m0, n0, tid,
                           sa, sa + (uint32_t)CAC<IM, KH>::A_U32 * 4u);
        }
        asm volatile("cp.async.commit_group;");

        uint32_t sbase = smem_base +
            (uint32_t)((t % CA_STAGES) * CAC<IM, KH>::STAGE_U32) * 4u;

#pragma unroll
        for (int ks = 0; ks < KH / 16; ks++) {
            uint32_t koff = (uint32_t)(ks * 32);
            uint32_t a[IM][4], b[8][2];
#pragma unroll
            for (int i = 0; i < IM; i++) {
                asm volatile(
                    "ldmatrix.sync.aligned.m8n8.x4.shared.b16 {%0,%1,%2,%3}, [%4];"
                    : "=r"(a[i][0]), "=r"(a[i][1]), "=r"(a[i][2]), "=r"(a[i][3])
                    : "r"(sbase + aoff[i] + koff));
            }
#pragma unroll
            for (int jp = 0; jp < 4; jp++) {
                asm volatile(
                    "ldmatrix.sync.aligned.m8n8.x4.shared.b16 {%0,%1,%2,%3}, [%4];"
                    : "=r"(b[2 * jp][0]), "=r"(b[2 * jp][1]),
                      "=r"(b[2 * jp + 1][0]), "=r"(b[2 * jp + 1][1])
                    : "r"(sbase + boff[jp] + koff));
            }
#pragma unroll
            for (int i = 0; i < IM; i++)
#pragma unroll
                for (int j = 0; j < 8; j++) {
                    asm volatile(
                        "mma.sync.aligned.m16n8k16.row.col.f32.f16.f16.f32 "
                        "{%0,%1,%2,%3}, {%4,%5,%6,%7}, {%8,%9}, {%0,%1,%2,%3};"
                        : "+f"(c[i][j][0]), "+f"(c[i][j][1]),
                          "+f"(c[i][j][2]), "+f"(c[i][j][3])
                        : "r"(a[i][0]), "r"(a[i][1]), "r"(a[i][2]), "r"(a[i][3]),
                          "r"(b[j][0]), "r"(b[j][1]));
                }
        }
    }

    // ---- epilogue ----
#pragma unroll
    for (int i = 0; i < IM; i++) {
        int r0 = m0 + wm * (IM * 16) + i * 16 + gid;
#pragma unroll
        for (int j = 0; j < 8; j++) {
            int c0 = n0 + wn * 64 + j * 8 + 2 * tig;
#pragma unroll
            for (int rr = 0; rr < 2; rr++) {
                int gm = r0 + rr * 8;
                if (gm >= M) continue;
#pragma unroll
                for (int cc = 0; cc < 2; cc++) {
                    int gn = c0 + cc;
                    if (gn >= N) continue;
                    float v = c[i][j][rr * 2 + cc];
                    if (bias) v += bias[gn];
                    if (relu) v = fmaxf(v, 0.f);
                    if (C) C[(long long)gm * ldc + gn] = v;
                    if (Ch) {
                        int col = gn;
                        if (qkvpad) {
                            int seg = (gn >= 2 * DD) ? 2 : (gn >= DD ? 1 : 0);
                            col = seg * DP + (gn - seg * DD);
                        }
                        Ch[(long long)gm * ldh + col] = __float2half_rn(v);
                    }
                }
            }
        }
    }
}

template <int IM, int KH>
__global__ __launch_bounds__(256, 2)
void hgemm(int M, int N, int K,
           const __half* __restrict__ A, long long lda, long long sA,
           const __half* __restrict__ B, long long ldb, long long sB,
           float* __restrict__ C, long long ldc, long long sC,
           __half* __restrict__ Ch, long long ldh, long long sCh,
           const float* __restrict__ bias, long long sBias,
           int relu, int qkvpad) {
    extern __shared__ uint32_t dsm[];
    int z = blockIdx.z;
    A += (long long)z * sA;
    B += (long long)z * sB;
    if (C) C += (long long)z * sC;
    if (Ch) Ch += (long long)z * sCh;
    if (bias) bias += (long long)z * sBias;
    hg_core<IM, KH>(M, N, K, A, lda, B, ldb, C, ldc, Ch, ldh, bias,
                    relu, qkvpad, blockIdx.y * (IM * 64), blockIdx.x * 128, dsm);
}

// ---- dual fp16 GEMM (S0 || VoT), IM=1/KH=64, z selects ----
struct HG {
    const __half* A; const __half* B; float* C; __half* Ch;
    long long lda, ldb, ldc, ldh;
    int M, N, K;
};

__global__ __launch_bounds__(256, 2)
void hg_dual(HG a0, HG a1) {
    extern __shared__ uint32_t dsm[];
    const HG& g = (blockIdx.z == 0) ? a0 : a1;
    hg_core<1, 64>(g.M, g.N, g.K, g.A, g.lda, g.B, g.ldb, g.C, g.ldc,
                   g.Ch, g.ldh, nullptr, 0, 0,
                   blockIdx.y * 64, blockIdx.x * 128, dsm);
}

// ================= thin GEMM body (M == 14, fp32) =================
__device__ __forceinline__ void thin_body(
    int bid, int N, int K,
    const float* __restrict__ A, long long lda,
    const float* __restrict__ B, long long ldb,
    float* __restrict__ C, long long ldc,
    const float* __restrict__ bias, float* sAm) {
    int tid = threadIdx.x;
    int K4 = K >> 2;
    for (int idx = tid; idx < NN * K4; idx += 256) {
        int m = idx / K4, k4 = idx - m * K4;
        *(float4*)&sAm[m * 816 + k4 * 4] =
            *(const float4*)(A + (long long)m * lda + k4 * 4);
    }
    __syncthreads();

    int n = bid * 8 + (tid >> 5);
    int lane = tid & 31;
    float acc[NN];
#pragma unroll
    for (int m = 0; m < NN; m++) acc[m] = 0.f;

    if (n < N) {
        const float* Bp = B + (long long)n * ldb;
        for (int k = lane * 4; k + 4 <= K; k += 128) {
            float4 bv = *(const float4*)(Bp + k);
#pragma unroll
            for (int m = 0; m < NN; m++) {
                float4 av = *(const float4*)&sAm[m * 816 + k];
                acc[m] += av.x * bv.x + av.y * bv.y + av.z * bv.z + av.w * bv.w;
            }
        }
    }
#pragma unroll
    for (int off = 16; off; off >>= 1)
#pragma unroll
        for (int m = 0; m < NN; m++)
            acc[m] += __shfl_down_sync(0xffffffffu, acc[m], off);

    if (lane == 0 && n < N) {
        float bz = bias ? bias[n] : 0.f;
#pragma unroll
        for (int m = 0; m < NN; m++)
            C[(long long)m * ldc + n] = acc[m] + bz;
    }
}

// ---- prep: fp16 converts (3 segs) + qkvt thin + edge_prep(+cmean) ----
struct CSeg { const float* src; __half* dst; int scols, ccols, dld; long long total; };
struct PrepArgs {
    CSeg s[3];
    int nb[3];
    const float* we; const float* inw; const float* inb; float* qkvt;
    const int* ei;
};

__global__ __launch_bounds__(256)
void prep_kernel(PrepArgs pa) {
    __shared__ float sAm[NN * 816];
    int bid = blockIdx.x;
#pragma unroll
    for (int k = 0; k < 3; k++) {
        if (bid < pa.nb[k]) {
            const CSeg& s = pa.s[k];
            long long base = (long long)bid * 1024 + threadIdx.x * 4;
#pragma unroll
            for (int e = 0; e < 4; e++) {
                long long i = base + e;
                if (i < s.total) {
                    int r = (int)(i / s.ccols), c = (int)(i % s.ccols);
                    s.dst[(long long)r * s.dld + c] =
                        __float2half_rn(s.src[(long long)r * s.scols + c]);
                }
            }
            return;
        }
        bid -= pa.nb[k];
    }
    const int NB_QKVT = (D3 + 7) / 8;
    if (bid < NB_QKVT) {
        thin_body(bid, D3, TXT, pa.we, TXT, pa.inw + IMG, DD,
                  pa.qkvt, D3, pa.inb, sAm);
        return;
    }
    if (threadIdx.x != 0) return;
    const int* ei = pa.ei;
    float deg[NN]; int cnt[NN];
    for (int n = 0; n < NN; n++) { deg[n] = 0.f; cnt[n] = 0; }
    for (int e = 0; e < EE; e++) { int d = ei[EE + e]; deg[d] += 1.f; cnt[d]++; }
    for (int n = 0; n < NN; n++) { deg[n] += 1.f; cnt[n]++; }
    float dinv[NN];
    for (int n = 0; n < NN; n++) dinv[n] = (deg[n] > 0.f) ? rsqrtf(deg[n]) : 0.f;
    int off = 0, pos[NN];
    for (int n = 0; n < NN; n++) { g_eoff[n] = off; pos[n] = off; off += cnt[n]; }
    g_eoff[NN] = off;
    for (int e = 0; e < EE; e++) {
        int d = ei[EE + e], s = ei[e];
        int p = pos[d]++;
        g_esrc[p] = s;
        g_ewt[p]  = dinv[s] * dinv[d];
    }
    for (int n = 0; n < NN; n++) {
        int p = pos[n]++;
        g_esrc[p] = n;
        g_ewt[p]  = dinv[n] * dinv[n];
    }
    float cm[NN];
    for (int n = 0; n < NN; n++) cm[n] = 0.f;
    for (int e = 0; e < EE + NN; e++) cm[g_esrc[e]] += g_ewt[e];
    for (int n = 0; n < NN; n++) g_cmean[n] = cm[n] / (float)NN;
}

// ---- fused transpose+fp16 multi (3 segments) ----
struct TSeg { const float* src; __half* dst; int R, C, dld, nbx, nby; };
struct TTab { TSeg s[3]; int nb[3]; };

__global__ void transpose_multi(TTab tt) {
    __shared__ float t[32][33];
    int bid = blockIdx.x;
    int seg = 0;
#pragma unroll
    for (int k = 0; k < 3; k++) {
        if (bid < tt.nb[k]) { seg = k; break; }
        bid -= tt.nb[k];
    }
    const TSeg& s = tt.s[seg];
    int bx = bid % s.nbx, by = bid / s.nbx;
    int c0 = bx * 32, r0 = by * 32;
    int x = threadIdx.x, y = threadIdx.y;
#pragma unroll
    for (int j = 0; j < 4; j++) {
        int r = r0 + y + j * 8;
        if (r < s.R && c0 + x < s.C)
            t[y + j * 8][x] = s.src[(long long)r * s.C + c0 + x];
    }
    __syncthreads();
#pragma unroll
    for (int j = 0; j < 4; j++) {
        int c = c0 + y + j * 8;
        if (c < s.C && r0 + x < s.R)
            s.dst[(long long)c * s.dld + r0 + x] = __float2half_rn(t[x][y + j * 8]);
    }
}

// ---- fused thin pair: Bq + ovt ----
struct TPairArgs {
    int nb0;
    int N0, K0; const float* A0; long long lda0; const float* B0; long long ldb0;
    float* C0; long long ldc0; const float* bias0;
    int N1, K1; const float* A1; long long lda1; const float* B1; long long ldb1;
    float* C1; long long ldc1; const float* bias1;
};

__global__ __launch_bounds__(256)
void thin_pair(TPairArgs t) {
    __shared__ float sAm[NN * 816];
    int bid = blockIdx.x;
    if (bid < t.nb0)
        thin_body(bid, t.N0, t.K0, t.A0, t.lda0, t.B0, t.ldb0,
                  t.C0, t.ldc0, t.bias0, sAm);
    else
        thin_body(bid - t.nb0, t.N1, t.K1, t.A1, t.lda1, t.B1, t.ldb1,
                  t.C1, t.ldc1, t.bias1, sAm);
}

// ------- softmax v2: one block per l, S0 row cached in smem ---
__global__ __launch_bounds__(256)
void softmax2(const float* __restrict__ S0, const float* __restrict__ Bq,
              __half* __restrict__ attn, float scale) {
    __shared__ float s0s[BB];
    __shared__ float sm[8];
    int l = blockIdx.x;
    int t = threadIdx.x;
    int lane = t & 31, wid = t >> 5;
    const float* s0 = S0 + (long long)l * BB;
#pragma unroll
    for (int i = 0; i < 4; i++) s0s[t + i * 256] = s0[t + i * 256];
    __syncthreads();

    for (int n = 0; n < NN; n++) {
        const float* bq = Bq + (long long)n * BB;
        float v[4];
#pragma unroll
        for (int i = 0; i < 4; i++) {
            int m = t + i * 256;
            v[i] = scale * (s0s[m] + bq[m]);
        }
        float mx = fmaxf(fmaxf(v[0], v[1]), fmaxf(v[2], v[3]));
#pragma unroll
        for (int o = 16; o; o >>= 1)
            mx = fmaxf(mx, __shfl_xor_sync(0xffffffffu, mx, o));
        if (!lane) sm[wid] = mx;
        __syncthreads();
        if (t == 0) {
            float m = sm[0];
            for (int i = 1; i < 8; i++) m = fmaxf(m, sm[i]);
            sm[0] = m;
        }
        __syncthreads();
        mx = sm[0];
        __syncthreads();

        float s = 0.f;
#pragma unroll
        for (int i = 0; i < 4; i++) { v[i] = __expf(v[i] - mx); s += v[i]; }
#pragma unroll
        for (int o = 16; o; o >>= 1) s += __shfl_xor_sync(0xffffffffu, s, o);
        if (!lane) sm[wid] = s;
        __syncthreads();
        if (t == 0) {
            float a = 0.f;
            for (int i = 0; i < 8; i++) a += sm[i];
            sm[0] = a;
        }
        __syncthreads();
        float inv = 1.f / sm[0];
        __half* out = attn + ((long long)n * BB + l) * BB;
#pragma unroll
        for (int i = 0; i < 4; i++)
            out[t + i * 256] = __float2half_rn(v[i] * inv);
        __syncthreads();
    }
}

// -------- LN1: x1 = LN(node + ao2_h); fp32 + fp16 copies -----------
__global__ void ln1_kernel(const float* __restrict__ img, const float* __restrict__ we,
                           const __half* __restrict__ R,
                           const float* __restrict__ g, const float* __restrict__ bb,
                           float* __restrict__ out, __half* __restrict__ outh) {
    const int D = DD;
    long long row = blockIdx.x;
    int b = (int)(row / NN);
    int n = (int)(row % NN);
    __shared__ float buf[DD];
    __shared__ float w1s[8], w2s[8];
    const float* ig = img + (long long)b * IMG;
    const float* w  = we + (long long)n * TXT;
    const __half* r = R + row * D;
    float s = 0.f, s2 = 0.f;
    for (int i = threadIdx.x; i < D; i += 256) {
        float nd = (i < IMG) ? ig[i] : w[i - IMG];
        float v = nd + __half2float(r[i]);
        buf[i] = v;
        s += v; s2 += v * v;
    }
#pragma unroll
    for (int o = 16; o; o >>= 1) {
        s  += __shfl_down_sync(0xffffffffu, s, o);
        s2 += __shfl_down_sync(0xffffffffu, s2, o);
    }
    int lane = threadIdx.x & 31, wid = threadIdx.x >> 5;
    if (!lane) { w1s[wid] = s; w2s[wid] = s2; }
    __syncthreads();
    if (threadIdx.x == 0) {
        float a = 0.f, b2 = 0.f;
        for (int i = 0; i < 8; i++) { a += w1s[i]; b2 += w2s[i]; }
        w1s[0] = a; w2s[0] = b2;
    }
    __syncthreads();
    float mean = w1s[0] / D;
    float var  = w2s[0] / D - mean * mean;
    float inv  = rsqrtf(var + 1e-5f);
    float* o = out + row * D;
    __half* oh = outh + row * DP;
    for (int i = threadIdx.x; i < D; i += 256) {
        float v = (buf[i] - mean) * inv * g[i] + bb[i];
        o[i] = v;
        oh[i] = __float2half_rn(v);
    }
}

// ---------------- LN2: x2_h = fp16(LN(X + R)) ----------------
__global__ void ln_kernel(const float* __restrict__ X, const float* __restrict__ R,
                          const float* __restrict__ g, const float* __restrict__ bb,
                          __half* __restrict__ outh) {
    const int D = DD;
    long long row = blockIdx.x;
    __shared__ float buf[DD];
    __shared__ float w1s[8], w2s[8];
    const float* x = X + row * D;
    const float* r = R + row * D;
    float s = 0.f, s2 = 0.f;
    for (int i = threadIdx.x; i < D; i += 256) {
        float v = x[i] + r[i];
        buf[i] = v;
        s += v; s2 += v * v;
    }
#pragma unroll
    for (int o = 16; o; o >>= 1) {
        s  += __shfl_down_sync(0xffffffffu, s, o);
        s2 += __shfl_down_sync(0xffffffffu, s2, o);
    }
    int lane = threadIdx.x & 31, wid = threadIdx.x >> 5;
    if (!lane) { w1s[wid] = s; w2s[wid] = s2; }
    __syncthreads();
    if (threadIdx.x == 0) {
        float a = 0.f, b2 = 0.f;
        for (int i = 0; i < 8; i++) { a += w1s[i]; b2 += w2s[i]; }
        w1s[0] = a; w2s[0] = b2;
    }
    __syncthreads();
    float mean = w1s[0] / D;
    float var  = w2s[0] / D - mean * mean;
    float inv  = rsqrtf(var + 1e-5f);
    __half* oh = outh + row * DP;
    for (int i = threadIdx.x; i < D; i += 256)
        oh[i] = __float2half_rn((buf[i] - mean) * inv * g[i] + bb[i]);
}

// ------ GCN tail: gsum[b][h] = sum_dst cmean[dst]*relu(agg(g1)[b,dst,h]+gb1[h])
__global__ __launch_bounds__(HID)
void gcn_gsum(const float* __restrict__ g1, const float* __restrict__ gb1,
              float* __restrict__ gsum) {
    __shared__ float sg[NN][HID];
    int b = blockIdx.x;
    int h = threadIdx.x;
    const float* base = g1 + (long long)b * NN * HID;
#pragma unroll
    for (int n = 0; n < NN; n++) sg[n][h] = base[n * HID + h];
    float bz = gb1[h];
    float acc = 0.f;
#pragma unroll
    for (int dst = 0; dst < NN; dst++) {
        float a = bz;
        int e0 = g_eoff[dst], e1 = g_eoff[dst + 1];
        for (int e = e0; e < e1; e++)
            a += g_ewt[e] * sg[g_esrc[e]][h];
        a = fmaxf(a, 0.f);
        acc += g_cmean[dst] * a;
    }
    gsum[(long long)b * HID + h] = acc;
}

// ---- fused pool+out: pool = relu(gsum@gw2+gb2); out = pool@lw+lb ----
// grid (8), 256 thr; each block: 128 rows, full HID cols (N=128 == tile).
__global__ __launch_bounds__(256)
void pool_out(const float* __restrict__ A,    // gsum [BB][HID]
              const float* __restrict__ Bw,   // gw2 [HID][HID], NT
              const float* __restrict__ gb2,
              const float* __restrict__ lw,   // [HID][CC]
              const float* __restrict__ lb,
              float* __restrict__ out) {
    const int BM = 128, BK = 8;
    __shared__ float As[BK][BM];
    __shared__ float Bs[BK][HID];

    int m0 = blockIdx.x * BM;
    int tid = threadIdx.x;
    int tx = tid & 15, ty = tid >> 4;
    int arow = tid >> 1, acol = (tid & 1) * 4;
    int bnrow = tid >> 5, bncol = (tid & 31) * 4;

    float acc[8][8];
#pragma unroll
    for (int i = 0; i < 8; i++)
#pragma unroll
        for (int j = 0; j < 8; j++) acc[i][j] = 0.f;

    for (int k0 = 0; k0 < HID; k0 += BK) {
        {
            int gm = m0 + arow, gk = k0 + acol;
            float4 v = *(const float4*)(A + (long long)gm * HID + gk);
            As[acol + 0][arow] = v.x; As[acol + 1][arow] = v.y;
            As[acol + 2][arow] = v.z; As[acol + 3][arow] = v.w;
        }
        {
            int gk = k0 + bnrow, gj = bncol;
            float4 v = *(const float4*)(Bw + (long long)gk * HID + gj);
            *(float4*)&Bs[bnrow][bncol] = v;
        }
        __syncthreads();

#pragma unroll
        for (int kk = 0; kk < BK; kk++) {
            float a[8], b[8];
#pragma unroll
            for (int i = 0; i < 8; i++) a[i] = As[kk][ty * 8 + i];
#pragma unroll
            for (int j = 0; j < 8; j++) b[j] = Bs[kk][tx * 8 + j];
#pragma unroll
            for (int i = 0; i < 8; i++)
#pragma unroll
                for (int j = 0; j < 8; j++) acc[i][j] = fmaf(a[i], b[j], acc[i][j]);
        }
        __syncthreads();
    }

    // pool = relu(acc + gb2); then out[m][c] = sum_h pool[m][h]*lw[h][c] + lb[c]
#pragma unroll
    for (int i = 0; i < 8; i++)
#pragma unroll
        for (int j = 0; j < 8; j++) {
            int gn = tx * 8 + j;
            acc[i][j] = fmaxf(acc[i][j] + gb2[gn], 0.f);
        }

    // reduce across the 16 tx-threads holding each row (contiguous lanes, width 16)
#pragma unroll
    for (int i = 0; i < 8; i++) {
        int gm = m0 + ty * 8 + i;
        for (int cB = 0; cB < CC; cB++) {
            float p = 0.f;
#pragma unroll
            for (int j = 0; j < 8; j++)
                p += acc[i][j] * lw[(tx * 8 + j) * CC + cB];
#pragma unroll
            for (int off = 8; off; off >>= 1)
                p += __shfl_down_sync(0xffffffffu, p, off, 16);
            if (tx == 0)
                out[(long long)gm * CC + cB] = p + lb[cB];
        }
    }
}

// ---------------- launch ----------------
static inline int ceil_div(int a, int b) { return (a + b - 1) / b; }

extern "C" void kernel_launch(void* const* d_in, const int* in_sizes, int n_in,
                              void* d_out, int out_size) {
    const float* img   = (const float*)d_in[0];
    const float* we    = (const float*)d_in[1];
    const int*   ei    = (const int*)  d_in[2];
    const float* inw   = (const float*)d_in[3];
    const float* inb   = (const float*)d_in[4];
    const float* outw  = (const float*)d_in[5];
    const float* outb  = (const float*)d_in[6];
    const float* ln1g  = (const float*)d_in[7];
    const float* ln1b  = (const float*)d_in[8];
    const float* ln2g  = (const float*)d_in[9];
    const float* ln2b  = (const float*)d_in[10];
    const float* w1    = (const float*)d_in[11];
    const float* b1    = (const float*)d_in[12];
    const float* w2    = (const float*)d_in[13];
    const float* b2    = (const float*)d_in[14];
    const float* gw1   = (const float*)d_in[15];
    const float* gb1   = (const float*)d_in[16];
    const float* gw2   = (const float*)d_in[17];
    const float* gb2   = (const float*)d_in[18];
    const float* lw    = (const float*)d_in[19];
    const float* lb    = (const float*)d_in[20];
    float* out = (float*)d_out;

    float *qkvi, *qkvt, *S0, *Bq, *ovt, *x1, *ff, *g1, *gsum;
    __half *imgr_h, *inwr_h, *outwr_h, *qkvi_h, *VoT_h, *attn_h, *ao2_h, *x1r_h;
    __half *w1t_h, *hid_h, *w2t_h, *x2_h, *gw1t_h;
    cudaGetSymbolAddress((void**)&qkvi, g_qkvi);
    cudaGetSymbolAddress((void**)&qkvt, g_qkvt);
    cudaGetSymbolAddress((void**)&S0,   g_S0);
    cudaGetSymbolAddress((void**)&Bq,   g_Bq);
    cudaGetSymbolAddress((void**)&ovt,  g_ovt);
    cudaGetSymbolAddress((void**)&x1,   g_x1);
    cudaGetSymbolAddress((void**)&ff,   g_ff);
    cudaGetSymbolAddress((void**)&g1,   g_g1);
    cudaGetSymbolAddress((void**)&gsum, g_gsum);
    cudaGetSymbolAddress((void**)&imgr_h,  g_imgr_h);
    cudaGetSymbolAddress((void**)&inwr_h,  g_inwr_h);
    cudaGetSymbolAddress((void**)&outwr_h, g_outwr_h);
    cudaGetSymbolAddress((void**)&qkvi_h,  g_qkvi_h);
    cudaGetSymbolAddress((void**)&VoT_h,   g_VoT_h);
    cudaGetSymbolAddress((void**)&attn_h,  g_attn_h);
    cudaGetSymbolAddress((void**)&ao2_h,   g_ao2_h);
    cudaGetSymbolAddress((void**)&x1r_h,   g_x1r_h);
    cudaGetSymbolAddress((void**)&w1t_h,   g_w1t_h);
    cudaGetSymbolAddress((void**)&hid_h,   g_hid_h);
    cudaGetSymbolAddress((void**)&w2t_h,   g_w2t_h);
    cudaGetSymbolAddress((void**)&x2_h,    g_x2_h);
    cudaGetSymbolAddress((void**)&gw1t_h,  g_gw1t_h);

    cudaFuncSetAttribute(hgemm<2, 64>,
                         cudaFuncAttributeMaxDynamicSharedMemorySize, CAC<2, 64>::SMEM);
    cudaFuncSetAttribute(hgemm<1, 64>,
                         cudaFuncAttributeMaxDynamicSharedMemorySize, CAC<1, 64>::SMEM);
    cudaFuncSetAttribute(hg_dual,
                         cudaFuncAttributeMaxDynamicSharedMemorySize, CAC<1, 64>::SMEM);

    const float attn_scale = 1.0f / sqrtf((float)DD);

    // 0) PREP: fp16 converts + qkvt thin + edge_prep(+cmean)
    {
        PrepArgs pa;
        pa.s[0] = { img,  imgr_h,  IMG, IMG, IMG, (long long)BB * IMG };
        pa.s[1] = { inw,  inwr_h,  DD,  IMG, IMG, (long long)D3 * IMG };
        pa.s[2] = { outw, outwr_h, DD,  DD,  DP,  (long long)DD * DD };
        int nblocks = 0;
        for (int k = 0; k < 3; k++) {
            pa.nb[k] = (int)((pa.s[k].total + 1023) / 1024);
            nblocks += pa.nb[k];
        }
        pa.we = we; pa.inw = inw; pa.inb = inb; pa.qkvt = qkvt; pa.ei = ei;
        nblocks += ceil_div(D3, 8) + 1;
        prep_kernel<<<nblocks, 256>>>(pa);
    }
    // 0b) transposed fp16 weights (one launch: w1, w2, gw1)
    {
        TTab tt;
        tt.s[0] = { w1,  w1t_h,  DD, FF,  DP, ceil_div(FF, 32),  ceil_div(DD, 32) };
        tt.s[1] = { w2,  w2t_h,  FF, DD,  FF, ceil_div(DD, 32),  ceil_div(FF, 32) };
        tt.s[2] = { gw1, gw1t_h, DD, HID, DP, ceil_div(HID, 32), ceil_div(DD, 32) };
        int nb = 0;
        for (int k = 0; k < 3; k++) {
            tt.nb[k] = tt.s[k].nbx * tt.s[k].nby;
            nb += tt.nb[k];
        }
        transpose_multi<<<nb, dim3(32, 8)>>>(tt);
    }

    // 1) qkvi = img @ Win[:, :512]^T  -> fp32 qkvi + padded fp16 qkvi_h
    hgemm<2, 64><<<dim3(ceil_div(D3, 128), 8, 1), 256, CAC<2, 64>::SMEM>>>(
        BB, D3, IMG, imgr_h, IMG, 0, inwr_h, IMG, 0,
        qkvi, D3, 0, qkvi_h, QLD, 0, nullptr, 0, 0, 1);

    // 2) DUAL: S0 = qi@ki^T (fp32) || VoT = Wout@vi^T (fp16)
    {
        HG a0, a1;
        a0.A = qkvi_h; a0.lda = QLD; a0.B = qkvi_h + DP; a0.ldb = QLD;
        a0.C = S0; a0.ldc = BB; a0.Ch = nullptr; a0.ldh = 0;
        a0.M = BB; a0.N = BB; a0.K = DD;
        a1.A = outwr_h; a1.lda = DP; a1.B = qkvi_h + 2 * DP; a1.ldb = QLD;
        a1.C = nullptr; a1.ldc = 0; a1.Ch = VoT_h; a1.ldh = BB;
        a1.M = DD; a1.N = BB; a1.K = DD;
        hg_dual<<<dim3(8, 16, 2), 256, CAC<1, 64>::SMEM>>>(a0, a1);
    }

    // 3) DUAL thin: Bq || ovt (fp32)
    {
        TPairArgs tp;
        tp.nb0 = ceil_div(BB, 8);
        tp.N0 = BB; tp.K0 = DD; tp.A0 = qkvt; tp.lda0 = D3;
        tp.B0 = qkvi + DD; tp.ldb0 = D3; tp.C0 = Bq; tp.ldc0 = BB; tp.bias0 = nullptr;
        tp.N1 = DD; tp.K1 = DD; tp.A1 = qkvt + 2 * DD; tp.lda1 = D3;
        tp.B1 = outw; tp.ldb1 = DD; tp.C1 = ovt; tp.ldc1 = DD; tp.bias1 = outb;
        thin_pair<<<tp.nb0 + ceil_div(DD, 8), 256>>>(tp);
    }

    // 4) attn_h = fp16(softmax(scale*(S0 + Bq)))  [1 block per l]
    softmax2<<<BB, 256>>>(S0, Bq, attn_h, attn_scale);

    // 5) ao2_h[l,n,:] = fp16(attn_n @ VoT^T + ovt[n])  (batched over n)
    hgemm<2, 64><<<dim3(ceil_div(DD, 128), 8, NN), 256, CAC<2, 64>::SMEM>>>(
        BB, DD, BB,
        attn_h, BB, (long long)BB * BB,
        VoT_h, BB, 0,
        nullptr, 0, 0,
        ao2_h, (long long)NN * DD, DD,
        ovt, DD, 0, 0);

    // 6) x1 = LN(node + ao2_h); x1r_h fp16
    ln1_kernel<<<MM, 256>>>(img, we, ao2_h, ln1g, ln1b, x1, x1r_h);

    // 7) hid_h = fp16(relu(x1r @ w1^T + b1))
    hgemm<2, 64><<<dim3(ceil_div(FF, 128), ceil_div(MM, 128), 1), 256, CAC<2, 64>::SMEM>>>(
        MM, FF, DD, x1r_h, DP, 0, w1t_h, DP, 0,
        nullptr, 0, 0, hid_h, FF, 0, b1, 0, 1, 0);

    // 8) ff = hid @ w2^T + b2 (fp32)
    hgemm<2, 64><<<dim3(ceil_div(DD, 128), ceil_div(MM, 128), 1), 256, CAC<2, 64>::SMEM>>>(
        MM, DD, FF, hid_h, FF, 0, w2t_h, FF, 0,
        ff, DD, 0, nullptr, 0, 0, b2, 0, 0, 0);

    // 9) x2_h = fp16(LN(x1 + ff))
    ln_kernel<<<MM, 256>>>(x1, ff, ln2g, ln2b, x2_h);

    // 10) g1 = x2 @ gw1^T (fp32)
    hgemm<1, 64><<<dim3(1, ceil_div(MM, 64), 1), 256, CAC<1, 64>::SMEM>>>(
        MM, HID, DD, x2_h, DP, 0, gw1t_h, DP, 0,
        g1, HID, 0, nullptr, 0, 0, nullptr, 0, 0, 0);

    // 11) gsum[b] = sum_n cmean[n]*relu(agg(g1)[b,n]+gb1)
    gcn_gsum<<<BB, HID>>>(g1, gb1, gsum);

    // 12) out = (relu(gsum @ gw2 + gb2)) @ lw + lb   (fused pool+out)
    pool_out<<<BB / 128, 256>>>(gsum, gw2, gb2, lw, lb, out);
}

// round 17
// speedup vs baseline: 1.2828x; 1.0002x over previous
#include <cuda_runtime.h>
#include <cuda_fp16.h>
#include <cstdint>
#include <math.h>

// ---------------- problem constants ----------------
#define BB   1024
#define IMG  512
#define TXT  300
#define NN   14
#define FF   2048
#define HID  128
#define CC   14
#define EE   182
#define DD   812     // IMG + TXT
#define D3   2436    // 3*D
#define MM   (BB*NN) // 14336 rows
#define DP   816     // DD padded to mult of 8
#define QLD  2448    // 3*DP, qkv fp16 row stride

// ---------------- fp32 scratch ----------------
__device__ float g_qkvi[(size_t)BB * D3];
__device__ float g_qkvt[(size_t)NN * D3];
__device__ float g_S0  [(size_t)BB * BB];
__device__ float g_Bq  [(size_t)NN * BB];
__device__ float g_ovt [(size_t)NN * DD];
__device__ float g_g1  [(size_t)MM * HID];
__device__ float g_gsum[(size_t)BB * HID];

// ---------------- fp16 scratch (tensor-core operands) ----------------
__device__ __align__(256) __half g_imgr_h [(size_t)BB * IMG];
__device__ __align__(256) __half g_inwr_h [(size_t)D3 * IMG];
__device__ __align__(256) __half g_outwr_h[(size_t)DD * DP];
__device__ __align__(256) __half g_qkvi_h [(size_t)BB * QLD];
__device__ __align__(256) __half g_VoT_h  [(size_t)DD * BB];
__device__ __align__(256) __half g_attn_h [(size_t)NN * BB * BB];
__device__ __align__(256) __half g_ao2_h  [(size_t)MM * DD];
__device__ __align__(256) __half g_x1r_h  [(size_t)MM * DP];
__device__ __align__(256) __half g_w1t_h  [(size_t)FF * DP];
__device__ __align__(256) __half g_hid_h  [(size_t)MM * FF];
__device__ __align__(256) __half g_w2t_h  [(size_t)DD * FF];
__device__ __align__(256) __half g_ff_h   [(size_t)MM * DD];
__device__ __align__(256) __half g_x2_h   [(size_t)MM * DP];
__device__ __align__(256) __half g_gw1t_h [(size_t)HID * DP];

__device__ int   g_eoff[NN + 1];
__device__ int   g_esrc[EE + NN + 16];
__device__ float g_ewt [EE + NN + 16];
__device__ float g_cmean[NN];

// ========== fp16 mma.sync GEMM (cp.async 3-stage, BT, ldmatrix frags) =======
#define CA_STAGES 3
template <int IM, int KH> struct CAC {
    static const int RS = KH / 2 + 4;
    static const int A_U32 = IM * 64 * RS;
    static const int STAGE_U32 = A_U32 + 128 * RS;
    static const int SMEM = CA_STAGES * STAGE_U32 * 4;
};

template <int IM, int KH>
__device__ __forceinline__ void hfetch(
    int k0, int M, int N, int K,
    const __half* __restrict__ A, long long lda,
    const __half* __restrict__ B, long long ldb,
    int m0, int n0, int tid, uint32_t sA, uint32_t sB) {
    const int RS = CAC<IM, KH>::RS;
    const int CPR = KH / 8;
    {
        const int TOT = IM * 64 * CPR;
#pragma unroll
        for (int c = 0; c < TOT / 256; c++) {
            int idx = c * 256 + tid;
            int row = idx / CPR, ch = idx - row * CPR;
            int gm = m0 + row;
            bool mv = gm < M;
            const __half* rp = A + (long long)(mv ? gm : m0) * lda;
            int kh = k0 + ch * 8;
            int rem = K - kh;
            int vb = mv ? (rem >= 8 ? 16 : (rem > 0 ? rem * 2 : 0)) : 0;
            const __half* src = rp + (kh < K ? kh : 0);
            uint32_t dst = sA + (uint32_t)(row * RS + ch * 4) * 4u;
            asm volatile("cp.async.cg.shared.global [%0], [%1], 16, %2;"
                         :: "r"(dst), "l"(src), "r"(vb));
        }
    }
    {
        const int TOT = 128 * CPR;
#pragma unroll
        for (int c = 0; c < TOT / 256; c++) {
            int idx = c * 256 + tid;
            int row = idx / CPR, ch = idx - row * CPR;
            int gj = n0 + row;
            bool nv = gj < N;
            const __half* rp = B + (long long)(nv ? gj : n0) * ldb;
            int kh = k0 + ch * 8;
            int rem = K - kh;
            int vb = nv ? (rem >= 8 ? 16 : (rem > 0 ? rem * 2 : 0)) : 0;
            const __half* src = rp + (kh < K ? kh : 0);
            uint32_t dst = sB + (uint32_t)(row * RS + ch * 4) * 4u;
            asm volatile("cp.async.cg.shared.global [%0], [%1], 16, %2;"
                         :: "r"(dst), "l"(src), "r"(vb));
        }
    }
}

template <int IM, int KH>
__device__ __forceinline__ void hg_core(
    int M, int N, int K,
    const __half* __restrict__ A, long long lda,
    const __half* __restrict__ B, long long ldb,
    float* __restrict__ C, long long ldc,
    __half* __restrict__ Ch, long long ldh,
    const float* __restrict__ bias,
    int relu, int qkvpad,
    int m0, int n0, uint32_t* dsm) {
    if (m0 >= M) return;
    const int RS = CAC<IM, KH>::RS;
    int tid = threadIdx.x;
    int warp = tid >> 5, lane = tid & 31;
    int wm = warp >> 1, wn = warp & 1;
    int gid = lane >> 2, tig = lane & 3;

    uint32_t smem_base = (uint32_t)__cvta_generic_to_shared(dsm);

    int a_row = (lane & 7) + ((lane >> 3) & 1) * 8;
    int a_col = (lane >> 4) * 4;
    int b_row = (lane & 7) + ((lane >> 4) & 1) * 8;
    int b_col = ((lane >> 3) & 1) * 4;

    uint32_t aoff[IM];
#pragma unroll
    for (int i = 0; i < IM; i++)
        aoff[i] = (uint32_t)(((wm * (IM * 16) + i * 16 + a_row) * RS + a_col) * 4);
    uint32_t boff[4];
#pragma unroll
    for (int jp = 0; jp < 4; jp++)
        boff[jp] = (uint32_t)(((wn * 64 + jp * 16 + b_row) * RS + b_col) * 4)
                   + (uint32_t)(CAC<IM, KH>::A_U32 * 4);

    float c[IM][8][4];
#pragma unroll
    for (int i = 0; i < IM; i++)
#pragma unroll
        for (int j = 0; j < 8; j++)
#pragma unroll
            for (int r = 0; r < 4; r++) c[i][j][r] = 0.f;

    int ntiles = (K + KH - 1) / KH;

#pragma unroll
    for (int t = 0; t < CA_STAGES - 1; t++) {
        if (t < ntiles) {
            uint32_t sa = smem_base + (uint32_t)(t * CAC<IM, KH>::STAGE_U32) * 4u;
            hfetch<IM, KH>(t * KH, M, N, K, A, lda, B, ldb, m0, n0, tid,
                           sa, sa + (uint32_t)CAC<IM, KH>::A_U32 * 4u);
        }
        asm volatile("cp.async.commit_group;");
    }

    for (int t = 0; t < ntiles; t++) {
        asm volatile("cp.async.wait_group %0;" :: "n"(CA_STAGES - 2));
        __syncthreads();

        int nf = t + CA_STAGES - 1;
        if (nf < ntiles) {
            uint32_t sa = smem_base +
                (uint32_t)((nf % CA_STAGES) * CAC<IM, KH>::STAGE_U32) * 4u;
            hfetch<IM, KH>(nf * KH, M, N, K, A, lda, B, ldb, m0, n0, tid,
                           sa, sa + (uint32_t)CAC<IM, KH>::A_U32 * 4u);
        }
        asm volatile("cp.async.commit_group;");

        uint32_t sbase = smem_base +
            (uint32_t)((t % CA_STAGES) * CAC<IM, KH>::STAGE_U32) * 4u;

#pragma unroll
        for (int ks = 0; ks < KH / 16; ks++) {
            uint32_t koff = (uint32_t)(ks * 32);
            uint32_t a[IM][4], b[8][2];
#pragma unroll
            for (int i = 0; i < IM; i++) {
                asm volatile(
                    "ldmatrix.sync.aligned.m8n8.x4.shared.b16 {%0,%1,%2,%3}, [%4];"
                    : "=r"(a[i][0]), "=r"(a[i][1]), "=r"(a[i][2]), "=r"(a[i][3])
                    : "r"(sbase + aoff[i] + koff));
            }
#pragma unroll
            for (int jp = 0; jp < 4; jp++) {
                asm volatile(
                    "ldmatrix.sync.aligned.m8n8.x4.shared.b16 {%0,%1,%2,%3}, [%4];"
                    : "=r"(b[2 * jp][0]), "=r"(b[2 * jp][1]),
                      "=r"(b[2 * jp + 1][0]), "=r"(b[2 * jp + 1][1])
                    : "r"(sbase + boff[jp] + koff));
            }
#pragma unroll
            for (int i = 0; i < IM; i++)
#pragma unroll
                for (int j = 0; j < 8; j++) {
                    asm volatile(
                        "mma.sync.aligned.m16n8k16.row.col.f32.f16.f16.f32 "
                        "{%0,%1,%2,%3}, {%4,%5,%6,%7}, {%8,%9}, {%0,%1,%2,%3};"
                        : "+f"(c[i][j][0]), "+f"(c[i][j][1]),
                          "+f"(c[i][j][2]), "+f"(c[i][j][3])
                        : "r"(a[i][0]), "r"(a[i][1]), "r"(a[i][2]), "r"(a[i][3]),
                          "r"(b[j][0]), "r"(b[j][1]));
                }
        }
    }

    // ---- epilogue ----
#pragma unroll
    for (int i = 0; i < IM; i++) {
        int r0 = m0 + wm * (IM * 16) + i * 16 + gid;
#pragma unroll
        for (int j = 0; j < 8; j++) {
            int c0 = n0 + wn * 64 + j * 8 + 2 * tig;
#pragma unroll
            for (int rr = 0; rr < 2; rr++) {
                int gm = r0 + rr * 8;
                if (gm >= M) continue;
#pragma unroll
                for (int cc = 0; cc < 2; cc++) {
                    int gn = c0 + cc;
                    if (gn >= N) continue;
                    float v = c[i][j][rr * 2 + cc];
                    if (bias) v += bias[gn];
                    if (relu) v = fmaxf(v, 0.f);
                    if (C) C[(long long)gm * ldc + gn] = v;
                    if (Ch) {
                        int col = gn;
                        if (qkvpad) {
                            int seg = (gn >= 2 * DD) ? 2 : (gn >= DD ? 1 : 0);
                            col = seg * DP + (gn - seg * DD);
                        }
                        Ch[(long long)gm * ldh + col] = __float2half_rn(v);
                    }
                }
            }
        }
    }
}

template <int IM, int KH>
__global__ __launch_bounds__(256, 2)
void hgemm(int M, int N, int K,
           const __half* __restrict__ A, long long lda, long long sA,
           const __half* __restrict__ B, long long ldb, long long sB,
           float* __restrict__ C, long long ldc, long long sC,
           __half* __restrict__ Ch, long long ldh, long long sCh,
           const float* __restrict__ bias, long long sBias,
           int relu, int qkvpad) {
    extern __shared__ uint32_t dsm[];
    int z = blockIdx.z;
    A += (long long)z * sA;
    B += (long long)z * sB;
    if (C) C += (long long)z * sC;
    if (Ch) Ch += (long long)z * sCh;
    if (bias) bias += (long long)z * sBias;
    hg_core<IM, KH>(M, N, K, A, lda, B, ldb, C, ldc, Ch, ldh, bias,
                    relu, qkvpad, blockIdx.y * (IM * 64), blockIdx.x * 128, dsm);
}

// ---- dual fp16 GEMM (S0 || VoT), IM=1/KH=64, z selects ----
struct HG {
    const __half* A; const __half* B; float* C; __half* Ch;
    long long lda, ldb, ldc, ldh;
    int M, N, K;
};

__global__ __launch_bounds__(256, 2)
void hg_dual(HG a0, HG a1) {
    extern __shared__ uint32_t dsm[];
    const HG& g = (blockIdx.z == 0) ? a0 : a1;
    hg_core<1, 64>(g.M, g.N, g.K, g.A, g.lda, g.B, g.ldb, g.C, g.ldc,
                   g.Ch, g.ldh, nullptr, 0, 0,
                   blockIdx.y * 64, blockIdx.x * 128, dsm);
}

// ================= thin GEMM body (M == 14, fp32) =================
__device__ __forceinline__ void thin_body(
    int bid, int N, int K,
    const float* __restrict__ A, long long lda,
    const float* __restrict__ B, long long ldb,
    float* __restrict__ C, long long ldc,
    const float* __restrict__ bias, float* sAm) {
    int tid = threadIdx.x;
    int K4 = K >> 2;
    for (int idx = tid; idx < NN * K4; idx += 256) {
        int m = idx / K4, k4 = idx - m * K4;
        *(float4*)&sAm[m * 816 + k4 * 4] =
            *(const float4*)(A + (long long)m * lda + k4 * 4);
    }
    __syncthreads();

    int n = bid * 8 + (tid >> 5);
    int lane = tid & 31;
    float acc[NN];
#pragma unroll
    for (int m = 0; m < NN; m++) acc[m] = 0.f;

    if (n < N) {
        const float* Bp = B + (long long)n * ldb;
        for (int k = lane * 4; k + 4 <= K; k += 128) {
            float4 bv = *(const float4*)(Bp + k);
#pragma unroll
            for (int m = 0; m < NN; m++) {
                float4 av = *(const float4*)&sAm[m * 816 + k];
                acc[m] += av.x * bv.x + av.y * bv.y + av.z * bv.z + av.w * bv.w;
            }
        }
    }
#pragma unroll
    for (int off = 16; off; off >>= 1)
#pragma unroll
        for (int m = 0; m < NN; m++)
            acc[m] += __shfl_down_sync(0xffffffffu, acc[m], off);

    if (lane == 0 && n < N) {
        float bz = bias ? bias[n] : 0.f;
#pragma unroll
        for (int m = 0; m < NN; m++)
            C[(long long)m * ldc + n] = acc[m] + bz;
    }
}

// ---- prep: fp16 converts (3 segs) + qkvt thin + edge_prep(+cmean) ----
struct CSeg { const float* src; __half* dst; int scols, ccols, dld; long long total; };
struct PrepArgs {
    CSeg s[3];
    int nb[3];
    const float* we; const float* inw; const float* inb; float* qkvt;
    const int* ei;
};

__global__ __launch_bounds__(256)
void prep_kernel(PrepArgs pa) {
    __shared__ float sAm[NN * 816];
    int bid = blockIdx.x;
#pragma unroll
    for (int k = 0; k < 3; k++) {
        if (bid < pa.nb[k]) {
            const CSeg& s = pa.s[k];
            long long base = (long long)bid * 1024 + threadIdx.x * 4;
#pragma unroll
            for (int e = 0; e < 4; e++) {
                long long i = base + e;
                if (i < s.total) {
                    int r = (int)(i / s.ccols), c = (int)(i % s.ccols);
                    s.dst[(long long)r * s.dld + c] =
                        __float2half_rn(s.src[(long long)r * s.scols + c]);
                }
            }
            return;
        }
        bid -= pa.nb[k];
    }
    const int NB_QKVT = (D3 + 7) / 8;
    if (bid < NB_QKVT) {
        thin_body(bid, D3, TXT, pa.we, TXT, pa.inw + IMG, DD,
                  pa.qkvt, D3, pa.inb, sAm);
        return;
    }
    if (threadIdx.x != 0) return;
    const int* ei = pa.ei;
    float deg[NN]; int cnt[NN];
    for (int n = 0; n < NN; n++) { deg[n] = 0.f; cnt[n] = 0; }
    for (int e = 0; e < EE; e++) { int d = ei[EE + e]; deg[d] += 1.f; cnt[d]++; }
    for (int n = 0; n < NN; n++) { deg[n] += 1.f; cnt[n]++; }
    float dinv[NN];
    for (int n = 0; n < NN; n++) dinv[n] = (deg[n] > 0.f) ? rsqrtf(deg[n]) : 0.f;
    int off = 0, pos[NN];
    for (int n = 0; n < NN; n++) { g_eoff[n] = off; pos[n] = off; off += cnt[n]; }
    g_eoff[NN] = off;
    for (int e = 0; e < EE; e++) {
        int d = ei[EE + e], s = ei[e];
        int p = pos[d]++;
        g_esrc[p] = s;
        g_ewt[p]  = dinv[s] * dinv[d];
    }
    for (int n = 0; n < NN; n++) {
        int p = pos[n]++;
        g_esrc[p] = n;
        g_ewt[p]  = dinv[n] * dinv[n];
    }
    float cm[NN];
    for (int n = 0; n < NN; n++) cm[n] = 0.f;
    for (int e = 0; e < EE + NN; e++) cm[g_esrc[e]] += g_ewt[e];
    for (int n = 0; n < NN; n++) g_cmean[n] = cm[n] / (float)NN;
}

// ---- fused transpose+fp16 multi (3 segments) ----
struct TSeg { const float* src; __half* dst; int R, C, dld, nbx, nby; };
struct TTab { TSeg s[3]; int nb[3]; };

__global__ void transpose_multi(TTab tt) {
    __shared__ float t[32][33];
    int bid = blockIdx.x;
    int seg = 0;
#pragma unroll
    for (int k = 0; k < 3; k++) {
        if (bid < tt.nb[k]) { seg = k; break; }
        bid -= tt.nb[k];
    }
    const TSeg& s = tt.s[seg];
    int bx = bid % s.nbx, by = bid / s.nbx;
    int c0 = bx * 32, r0 = by * 32;
    int x = threadIdx.x, y = threadIdx.y;
#pragma unroll
    for (int j = 0; j < 4; j++) {
        int r = r0 + y + j * 8;
        if (r < s.R && c0 + x < s.C)
            t[y + j * 8][x] = s.src[(long long)r * s.C + c0 + x];
    }
    __syncthreads();
#pragma unroll
    for (int j = 0; j < 4; j++) {
        int c = c0 + y + j * 8;
        if (c < s.C && r0 + x < s.R)
            s.dst[(long long)c * s.dld + r0 + x] = __float2half_rn(t[x][y + j * 8]);
    }
}

// ---- fused thin pair: Bq + ovt ----
struct TPairArgs {
    int nb0;
    int N0, K0; const float* A0; long long lda0; const float* B0; long long ldb0;
    float* C0; long long ldc0; const float* bias0;
    int N1, K1; const float* A1; long long lda1; const float* B1; long long ldb1;
    float* C1; long long ldc1; const float* bias1;
};

__global__ __launch_bounds__(256)
void thin_pair(TPairArgs t) {
    __shared__ float sAm[NN * 816];
    int bid = blockIdx.x;
    if (bid < t.nb0)
        thin_body(bid, t.N0, t.K0, t.A0, t.lda0, t.B0, t.ldb0,
                  t.C0, t.ldc0, t.bias0, sAm);
    else
        thin_body(bid - t.nb0, t.N1, t.K1, t.A1, t.lda1, t.B1, t.ldb1,
                  t.C1, t.ldc1, t.bias1, sAm);
}

// ------- softmax v2: one block per l, S0 row cached in smem ---
__global__ __launch_bounds__(256)
void softmax2(const float* __restrict__ S0, const float* __restrict__ Bq,
              __half* __restrict__ attn, float scale) {
    __shared__ float s0s[BB];
    __shared__ float sm[8];
    int l = blockIdx.x;
    int t = threadIdx.x;
    int lane = t & 31, wid = t >> 5;
    const float* s0 = S0 + (long long)l * BB;
#pragma unroll
    for (int i = 0; i < 4; i++) s0s[t + i * 256] = s0[t + i * 256];
    __syncthreads();

    for (int n = 0; n < NN; n++) {
        const float* bq = Bq + (long long)n * BB;
        float v[4];
#pragma unroll
        for (int i = 0; i < 4; i++) {
            int m = t + i * 256;
            v[i] = scale * (s0s[m] + bq[m]);
        }
        float mx = fmaxf(fmaxf(v[0], v[1]), fmaxf(v[2], v[3]));
#pragma unroll
        for (int o = 16; o; o >>= 1)
            mx = fmaxf(mx, __shfl_xor_sync(0xffffffffu, mx, o));
        if (!lane) sm[wid] = mx;
        __syncthreads();
        if (t == 0) {
            float m = sm[0];
            for (int i = 1; i < 8; i++) m = fmaxf(m, sm[i]);
            sm[0] = m;
        }
        __syncthreads();
        mx = sm[0];
        __syncthreads();

        float s = 0.f;
#pragma unroll
        for (int i = 0; i < 4; i++) { v[i] = __expf(v[i] - mx); s += v[i]; }
#pragma unroll
        for (int o = 16; o; o >>= 1) s += __shfl_xor_sync(0xffffffffu, s, o);
        if (!lane) sm[wid] = s;
        __syncthreads();
        if (t == 0) {
            float a = 0.f;
            for (int i = 0; i < 8; i++) a += sm[i];
            sm[0] = a;
        }
        __syncthreads();
        float inv = 1.f / sm[0];
        __half* out = attn + ((long long)n * BB + l) * BB;
#pragma unroll
        for (int i = 0; i < 4; i++)
            out[t + i * 256] = __float2half_rn(v[i] * inv);
        __syncthreads();
    }
}

// -------- LN1: x1r_h = fp16(LN(node + ao2_h)) -----------
__global__ void ln1_kernel(const float* __restrict__ img, const float* __restrict__ we,
                           const __half* __restrict__ R,
                           const float* __restrict__ g, const float* __restrict__ bb,
                           __half* __restrict__ outh) {
    const int D = DD;
    long long row = blockIdx.x;
    int b = (int)(row / NN);
    int n = (int)(row % NN);
    __shared__ float buf[DD];
    __shared__ float w1s[8], w2s[8];
    const float* ig = img + (long long)b * IMG;
    const float* w  = we + (long long)n * TXT;
    const __half* r = R + row * D;
    float s = 0.f, s2 = 0.f;
    for (int i = threadIdx.x; i < D; i += 256) {
        float nd = (i < IMG) ? ig[i] : w[i - IMG];
        float v = nd + __half2float(r[i]);
        buf[i] = v;
        s += v; s2 += v * v;
    }
#pragma unroll
    for (int o = 16; o; o >>= 1) {
        s  += __shfl_down_sync(0xffffffffu, s, o);
        s2 += __shfl_down_sync(0xffffffffu, s2, o);
    }
    int lane = threadIdx.x & 31, wid = threadIdx.x >> 5;
    if (!lane) { w1s[wid] = s; w2s[wid] = s2; }
    __syncthreads();
    if (threadIdx.x == 0) {
        float a = 0.f, b2 = 0.f;
        for (int i = 0; i < 8; i++) { a += w1s[i]; b2 += w2s[i]; }
        w1s[0] = a; w2s[0] = b2;
    }
    __syncthreads();
    float mean = w1s[0] / D;
    float var  = w2s[0] / D - mean * mean;
    float inv  = rsqrtf(var + 1e-5f);
    __half* oh = outh + row * DP;
    for (int i = threadIdx.x; i < D; i += 256)
        oh[i] = __float2half_rn((buf[i] - mean) * inv * g[i] + bb[i]);
}

// ---------------- LN2: x2_h = fp16(LN(x1r_h + ff_h)) ----------------
__global__ void ln_kernel(const __half* __restrict__ X, const __half* __restrict__ R,
                          const float* __restrict__ g, const float* __restrict__ bb,
                          __half* __restrict__ outh) {
    const int D = DD;
    long long row = blockIdx.x;
    __shared__ float buf[DD];
    __shared__ float w1s[8], w2s[8];
    const __half* x = X + row * DP;
    const __half* r = R + row * D;
    float s = 0.f, s2 = 0.f;
    for (int i = threadIdx.x; i < D; i += 256) {
        float v = __half2float(x[i]) + __half2float(r[i]);
        buf[i] = v;
        s += v; s2 += v * v;
    }
#pragma unroll
    for (int o = 16; o; o >>= 1) {
        s  += __shfl_down_sync(0xffffffffu, s, o);
        s2 += __shfl_down_sync(0xffffffffu, s2, o);
    }
    int lane = threadIdx.x & 31, wid = threadIdx.x >> 5;
    if (!lane) { w1s[wid] = s; w2s[wid] = s2; }
    __syncthreads();
    if (threadIdx.x == 0) {
        float a = 0.f, b2 = 0.f;
        for (int i = 0; i < 8; i++) { a += w1s[i]; b2 += w2s[i]; }
        w1s[0] = a; w2s[0] = b2;
    }
    __syncthreads();
    float mean = w1s[0] / D;
    float var  = w2s[0] / D - mean * mean;
    float inv  = rsqrtf(var + 1e-5f);
    __half* oh = outh + row * DP;
    for (int i = threadIdx.x; i < D; i += 256)
        oh[i] = __float2half_rn((buf[i] - mean) * inv * g[i] + bb[i]);
}

// ------ GCN tail: gsum[b][h] = sum_dst cmean[dst]*relu(agg(g1)[b,dst,h]+gb1[h])
__global__ __launch_bounds__(HID)
void gcn_gsum(const float* __restrict__ g1, const float* __restrict__ gb1,
              float* __restrict__ gsum) {
    __shared__ float sg[NN][HID];
    int b = blockIdx.x;
    int h = threadIdx.x;
    const float* base = g1 + (long long)b * NN * HID;
#pragma unroll
    for (int n = 0; n < NN; n++) sg[n][h] = base[n * HID + h];
    float bz = gb1[h];
    float acc = 0.f;
#pragma unroll
    for (int dst = 0; dst < NN; dst++) {
        float a = bz;
        int e0 = g_eoff[dst], e1 = g_eoff[dst + 1];
        for (int e = e0; e < e1; e++)
            a += g_ewt[e] * sg[g_esrc[e]][h];
        a = fmaxf(a, 0.f);
        acc += g_cmean[dst] * a;
    }
    gsum[(long long)b * HID + h] = acc;
}

// ---- fused pool+out: pool = relu(gsum@gw2+gb2); out = pool@lw+lb ----
__global__ __launch_bounds__(256)
void pool_out(const float* __restrict__ A,
              const float* __restrict__ Bw,
              const float* __restrict__ gb2,
              const float* __restrict__ lw,
              const float* __restrict__ lb,
              float* __restrict__ out) {
    const int BM = 128, BK = 8;
    __shared__ float As[BK][BM];
    __shared__ float Bs[BK][HID];

    int m0 = blockIdx.x * BM;
    int tid = threadIdx.x;
    int tx = tid & 15, ty = tid >> 4;
    int arow = tid >> 1, acol = (tid & 1) * 4;
    int bnrow = tid >> 5, bncol = (tid & 31) * 4;

    float acc[8][8];
#pragma unroll
    for (int i = 0; i < 8; i++)
#pragma unroll
        for (int j = 0; j < 8; j++) acc[i][j] = 0.f;

    for (int k0 = 0; k0 < HID; k0 += BK) {
        {
            int gm = m0 + arow, gk = k0 + acol;
            float4 v = *(const float4*)(A + (long long)gm * HID + gk);
            As[acol + 0][arow] = v.x; As[acol + 1][arow] = v.y;
            As[acol + 2][arow] = v.z; As[acol + 3][arow] = v.w;
        }
        {
            int gk = k0 + bnrow, gj = bncol;
            float4 v = *(const float4*)(Bw + (long long)gk * HID + gj);
            *(float4*)&Bs[bnrow][bncol] = v;
        }
        __syncthreads();

#pragma unroll
        for (int kk = 0; kk < BK; kk++) {
            float a[8], b[8];
#pragma unroll
            for (int i = 0; i < 8; i++) a[i] = As[kk][ty * 8 + i];
#pragma unroll
            for (int j = 0; j < 8; j++) b[j] = Bs[kk][tx * 8 + j];
#pragma unroll
            for (int i = 0; i < 8; i++)
#pragma unroll
                for (int j = 0; j < 8; j++) acc[i][j] = fmaf(a[i], b[j], acc[i][j]);
        }
        __syncthreads();
    }

#pragma unroll
    for (int i = 0; i < 8; i++)
#pragma unroll
        for (int j = 0; j < 8; j++) {
            int gn = tx * 8 + j;
            acc[i][j] = fmaxf(acc[i][j] + gb2[gn], 0.f);
        }

#pragma unroll
    for (int i = 0; i < 8; i++) {
        int gm = m0 + ty * 8 + i;
        for (int cB = 0; cB < CC; cB++) {
            float p = 0.f;
#pragma unroll
            for (int j = 0; j < 8; j++)
                p += acc[i][j] * lw[(tx * 8 + j) * CC + cB];
#pragma unroll
            for (int off = 8; off; off >>= 1)
                p += __shfl_down_sync(0xffffffffu, p, off, 16);
            if (tx == 0)
                out[(long long)gm * CC + cB] = p + lb[cB];
        }
    }
}

// ---------------- launch ----------------
static inline int ceil_div(int a, int b) { return (a + b - 1) / b; }

extern "C" void kernel_launch(void* const* d_in, const int* in_sizes, int n_in,
                              void* d_out, int out_size) {
    const float* img   = (const float*)d_in[0];
    const float* we    = (const float*)d_in[1];
    const int*   ei    = (const int*)  d_in[2];
    const float* inw   = (const float*)d_in[3];
    const float* inb   = (const float*)d_in[4];
    const float* outw  = (const float*)d_in[5];
    const float* outb  = (const float*)d_in[6];
    const float* ln1g  = (const float*)d_in[7];
    const float* ln1b  = (const float*)d_in[8];
    const float* ln2g  = (const float*)d_in[9];
    const float* ln2b  = (const float*)d_in[10];
    const float* w1    = (const float*)d_in[11];
    const float* b1    = (const float*)d_in[12];
    const float* w2    = (const float*)d_in[13];
    const float* b2    = (const float*)d_in[14];
    const float* gw1   = (const float*)d_in[15];
    const float* gb1   = (const float*)d_in[16];
    const float* gw2   = (const float*)d_in[17];
    const float* gb2   = (const float*)d_in[18];
    const float* lw    = (const float*)d_in[19];
    const float* lb    = (const float*)d_in[20];
    float* out = (float*)d_out;

    float *qkvi, *qkvt, *S0, *Bq, *ovt, *g1, *gsum;
    __half *imgr_h, *inwr_h, *outwr_h, *qkvi_h, *VoT_h, *attn_h, *ao2_h, *x1r_h;
    __half *w1t_h, *hid_h, *w2t_h, *ff_h, *x2_h, *gw1t_h;
    cudaGetSymbolAddress((void**)&qkvi, g_qkvi);
    cudaGetSymbolAddress((void**)&qkvt, g_qkvt);
    cudaGetSymbolAddress((void**)&S0,   g_S0);
    cudaGetSymbolAddress((void**)&Bq,   g_Bq);
    cudaGetSymbolAddress((void**)&ovt,  g_ovt);
    cudaGetSymbolAddress((void**)&g1,   g_g1);
    cudaGetSymbolAddress((void**)&gsum, g_gsum);
    cudaGetSymbolAddress((void**)&imgr_h,  g_imgr_h);
    cudaGetSymbolAddress((void**)&inwr_h,  g_inwr_h);
    cudaGetSymbolAddress((void**)&outwr_h, g_outwr_h);
    cudaGetSymbolAddress((void**)&qkvi_h,  g_qkvi_h);
    cudaGetSymbolAddress((void**)&VoT_h,   g_VoT_h);
    cudaGetSymbolAddress((void**)&attn_h,  g_attn_h);
    cudaGetSymbolAddress((void**)&ao2_h,   g_ao2_h);
    cudaGetSymbolAddress((void**)&x1r_h,   g_x1r_h);
    cudaGetSymbolAddress((void**)&w1t_h,   g_w1t_h);
    cudaGetSymbolAddress((void**)&hid_h,   g_hid_h);
    cudaGetSymbolAddress((void**)&w2t_h,   g_w2t_h);
    cudaGetSymbolAddress((void**)&ff_h,    g_ff_h);
    cudaGetSymbolAddress((void**)&x2_h,    g_x2_h);
    cudaGetSymbolAddress((void**)&gw1t_h,  g_gw1t_h);

    cudaFuncSetAttribute(hgemm<2, 64>,
                         cudaFuncAttributeMaxDynamicSharedMemorySize, CAC<2, 64>::SMEM);
    cudaFuncSetAttribute(hgemm<1, 64>,
                         cudaFuncAttributeMaxDynamicSharedMemorySize, CAC<1, 64>::SMEM);
    cudaFuncSetAttribute(hg_dual,
                         cudaFuncAttributeMaxDynamicSharedMemorySize, CAC<1, 64>::SMEM);

    const float attn_scale = 1.0f / sqrtf((float)DD);

    // 0) PREP: fp16 converts + qkvt thin + edge_prep(+cmean)
    {
        PrepArgs pa;
        pa.s[0] = { img,  imgr_h,  IMG, IMG, IMG, (long long)BB * IMG };
        pa.s[1] = { inw,  inwr_h,  DD,  IMG, IMG, (long long)D3 * IMG };
        pa.s[2] = { outw, outwr_h, DD,  DD,  DP,  (long long)DD * DD };
        int nblocks = 0;
        for (int k = 0; k < 3; k++) {
            pa.nb[k] = (int)((pa.s[k].total + 1023) / 1024);
            nblocks += pa.nb[k];
        }
        pa.we = we; pa.inw = inw; pa.inb = inb; pa.qkvt = qkvt; pa.ei = ei;
        nblocks += ceil_div(D3, 8) + 1;
        prep_kernel<<<nblocks, 256>>>(pa);
    }
    // 0b) transposed fp16 weights (one launch: w1, w2, gw1)
    {
        TTab tt;
        tt.s[0] = { w1,  w1t_h,  DD, FF,  DP, ceil_div(FF, 32),  ceil_div(DD, 32) };
        tt.s[1] = { w2,  w2t_h,  FF, DD,  FF, ceil_div(DD, 32),  ceil_div(FF, 32) };
        tt.s[2] = { gw1, gw1t_h, DD, HID, DP, ceil_div(HID, 32), ceil_div(DD, 32) };
        int nb = 0;
        for (int k = 0; k < 3; k++) {
            tt.nb[k] = tt.s[k].nbx * tt.s[k].nby;
            nb += tt.nb[k];
        }
        transpose_multi<<<nb, dim3(32, 8)>>>(tt);
    }

    // 1) qkvi = img @ Win[:, :512]^T  -> fp32 qkvi + padded fp16 qkvi_h
    hgemm<2, 64><<<dim3(ceil_div(D3, 128), 8, 1), 256, CAC<2, 64>::SMEM>>>(
        BB, D3, IMG, imgr_h, IMG, 0, inwr_h, IMG, 0,
        qkvi, D3, 0, qkvi_h, QLD, 0, nullptr, 0, 0, 1);

    // 2) DUAL: S0 = qi@ki^T (fp32) || VoT = Wout@vi^T (fp16)
    {
        HG a0, a1;
        a0.A = qkvi_h; a0.lda = QLD; a0.B = qkvi_h + DP; a0.ldb = QLD;
        a0.C = S0; a0.ldc = BB; a0.Ch = nullptr; a0.ldh = 0;
        a0.M = BB; a0.N = BB; a0.K = DD;
        a1.A = outwr_h; a1.lda = DP; a1.B = qkvi_h + 2 * DP; a1.ldb = QLD;
        a1.C = nullptr; a1.ldc = 0; a1.Ch = VoT_h; a1.ldh = BB;
        a1.M = DD; a1.N = BB; a1.K = DD;
        hg_dual<<<dim3(8, 16, 2), 256, CAC<1, 64>::SMEM>>>(a0, a1);
    }

    // 3) DUAL thin: Bq || ovt (fp32)
    {
        TPairArgs tp;
        tp.nb0 = ceil_div(BB, 8);
        tp.N0 = BB; tp.K0 = DD; tp.A0 = qkvt; tp.lda0 = D3;
        tp.B0 = qkvi + DD; tp.ldb0 = D3; tp.C0 = Bq; tp.ldc0 = BB; tp.bias0 = nullptr;
        tp.N1 = DD; tp.K1 = DD; tp.A1 = qkvt + 2 * DD; tp.lda1 = D3;
        tp.B1 = outw; tp.ldb1 = DD; tp.C1 = ovt; tp.ldc1 = DD; tp.bias1 = outb;
        thin_pair<<<tp.nb0 + ceil_div(DD, 8), 256>>>(tp);
    }

    // 4) attn_h = fp16(softmax(scale*(S0 + Bq)))  [1 block per l]
    softmax2<<<BB, 256>>>(S0, Bq, attn_h, attn_scale);

    // 5) ao2_h[l,n,:] = fp16(attn_n @ VoT^T + ovt[n])  (batched over n)
    hgemm<2, 64><<<dim3(ceil_div(DD, 128), 8, NN), 256, CAC<2, 64>::SMEM>>>(
        BB, DD, BB,
        attn_h, BB, (long long)BB * BB,
        VoT_h, BB, 0,
        nullptr, 0, 0,
        ao2_h, (long long)NN * DD, DD,
        ovt, DD, 0, 0);

    // 6) x1r_h = fp16(LN(node + ao2_h))
    ln1_kernel<<<MM, 256>>>(img, we, ao2_h, ln1g, ln1b, x1r_h);

    // 7) hid_h = fp16(relu(x1r @ w1^T + b1))
    hgemm<2, 64><<<dim3(ceil_div(FF, 128), ceil_div(MM, 128), 1), 256, CAC<2, 64>::SMEM>>>(
        MM, FF, DD, x1r_h, DP, 0, w1t_h, DP, 0,
        nullptr, 0, 0, hid_h, FF, 0, b1, 0, 1, 0);

    // 8) ff_h = fp16(hid @ w2^T + b2)
    hgemm<2, 64><<<dim3(ceil_div(DD, 128), ceil_div(MM, 128), 1), 256, CAC<2, 64>::SMEM>>>(
        MM, DD, FF, hid_h, FF, 0, w2t_h, FF, 0,
        nullptr, 0, 0, ff_h, DD, 0, b2, 0, 0, 0);

    // 9) x2_h = fp16(LN(x1r_h + ff_h))
    ln_kernel<<<MM, 256>>>(x1r_h, ff_h, ln2g, ln2b, x2_h);

    // 10) g1 = x2 @ gw1^T (fp32)
    hgemm<1, 64><<<dim3(1, ceil_div(MM, 64), 1), 256, CAC<1, 64>::SMEM>>>(
        MM, HID, DD, x2_h, DP, 0, gw1t_h, DP, 0,
        g1, HID, 0, nullptr, 0, 0, nullptr, 0, 0, 0);

    // 11) gsum[b] = sum_n cmean[n]*relu(agg(g1)[b,n]+gb1)
    gcn_gsum<<<BB, HID>>>(g1, gb1, gsum);

    // 12) out = (relu(gsum @ gw2 + gb2)) @ lw + lb   (fused pool+out)
    pool_out<<<BB / 128, 256>>>(gsum, gw2, gb2, lw, lb, out);
}